// round 12
// baseline (speedup 1.0000x reference)
#include <cuda_runtime.h>
#include <cuda_fp16.h>
#include <cstdint>

// ---------------------------------------------------------------------------
// Problem constants
// ---------------------------------------------------------------------------
#define N_NODES 500000
#define S_SAMPLE 100000
#define EQCAP 32768
#define OUT_C 256
#define IN_C 256
#define M_TILE 64
#define NBLK ((S_SAMPLE + M_TILE - 1) / M_TILE)   // 1563
#define NZERO 1024
#define NTOT (NBLK + NZERO)                       // 2587

// libdevice accurate log (immune to fast-math logf substitution)
extern "C" __device__ float __nv_logf(float);

// ---------------------------------------------------------------------------
// Device scratch
// ---------------------------------------------------------------------------
__device__ unsigned g_keys[N_NODES];
__device__ unsigned char g_flag[N_NODES];
__device__ int g_sel[S_SAMPLE + M_TILE];
__device__ uint2 g_eqPair[EQCAP];           // (key, idx)
__device__ unsigned g_c256[256];
__device__ unsigned g_m256[256];
__device__ unsigned g_B0;
__device__ unsigned g_P16;
__device__ int g_counters[4];
__device__ unsigned g_done[2];
__device__ unsigned g_wh[32768];            // w as f16 pairs, [k][n]
#define C_SEL 0
#define C_EQ 1
#define C_REM 2

// ---------------------------------------------------------------------------
// Threefry-2x32, partitionable: x0=0, x1=i, key=(0,42); draw = out0 ^ out1
// ---------------------------------------------------------------------------
__device__ __forceinline__ unsigned rotl32(unsigned x, int r) {
    return (x << r) | (x >> (32 - r));
}
__device__ __forceinline__ unsigned threefry_bits(unsigned i) {
    const unsigned ks0 = 0u, ks1 = 42u;
    const unsigned ks2 = 0x1BD11BDAu ^ ks0 ^ ks1;
    unsigned x0 = 0u + ks0;
    unsigned x1 = i + ks1;
#define TF_R4(a, b, c, d)                                   \
    x0 += x1; x1 = rotl32(x1, a); x1 ^= x0;                 \
    x0 += x1; x1 = rotl32(x1, b); x1 ^= x0;                 \
    x0 += x1; x1 = rotl32(x1, c); x1 ^= x0;                 \
    x0 += x1; x1 = rotl32(x1, d); x1 ^= x0;
    TF_R4(13, 15, 26, 6)  x0 += ks1; x1 += ks2 + 1u;
    TF_R4(17, 29, 16, 24) x0 += ks2; x1 += ks0 + 2u;
    TF_R4(13, 15, 26, 6)  x0 += ks0; x1 += ks1 + 3u;
    TF_R4(17, 29, 16, 24) x0 += ks1; x1 += ks2 + 4u;
    TF_R4(13, 15, 26, 6)  x0 += ks2; x1 += ks0 + 5u;
#undef TF_R4
    return x0 ^ x1;
}
__device__ __forceinline__ unsigned f2key(float f) {
    unsigned b = __float_as_uint(f);
    return (b & 0x80000000u) ? ~b : (b | 0x80000000u);
}

// ---------------------------------------------------------------------------
// suffix-scan pick over a 256-bin hist (in-block)
// ---------------------------------------------------------------------------
__device__ void pick256(const unsigned* hist, unsigned need,
                        unsigned* out_bin, unsigned* out_rem, unsigned* suf) {
    int t = threadIdx.x;
    suf[t] = hist[t];
    __syncthreads();
#pragma unroll
    for (int off = 1; off < 256; off <<= 1) {
        unsigned v = (t + off < 256) ? suf[t + off] : 0u;
        __syncthreads();
        suf[t] += v;
        __syncthreads();
    }
    unsigned above = (t < 255) ? suf[t + 1] : 0u;
    if (suf[t] >= need && above < need) {
        *out_bin = (unsigned)t;
        *out_rem = need - above;
        __threadfence();
    }
    __syncthreads();
}

// ---------------------------------------------------------------------------
// prep: zero counters + convert w to f16
// ---------------------------------------------------------------------------
__global__ void prep_kernel(const float* __restrict__ w) {
    int t = blockIdx.x * blockDim.x + threadIdx.x;   // 32768 threads
    if (t < 256) { g_c256[t] = 0; g_m256[t] = 0; }
    if (t < 4) g_counters[t] = 0;
    if (t < 2) g_done[t] = 0;
    float2 v = ((const float2*)w)[t];
    __half2 h = __floats2half2_rn(v.x, v.y);
    g_wh[t] = *(unsigned*)&h;
}

// ---------------------------------------------------------------------------
// score: keys + shared coarse hist (bits[31:24]) + fused pick8 in tail block
// ---------------------------------------------------------------------------
__global__ void score_kernel(const float* __restrict__ imp) {
    __shared__ unsigned sh[256];
    __shared__ unsigned is_last;
    int tid = threadIdx.x;
    sh[tid] = 0;
    if (tid == 0) is_last = 0;
    __syncthreads();
    int i = blockIdx.x * blockDim.x + tid;
    if (i < N_NODES) {
        unsigned bits = threefry_bits((unsigned)i);
        float f = __uint_as_float((bits >> 9) | 0x3F800000u) - 1.0f;
        float u = f + 1.17549435e-38f;
        float g = -__nv_logf(-__nv_logf(u));
        unsigned k = f2key(__nv_logf(imp[i]) + g);
        g_keys[i] = k;
        atomicAdd(&sh[k >> 24], 1u);
    }
    __syncthreads();
    if (sh[tid]) atomicAdd(&g_c256[tid], sh[tid]);
    __threadfence();
    __syncthreads();
    if (tid == 0) {
        unsigned old = atomicAdd(&g_done[0], 1u);
        if (old == gridDim.x - 1) is_last = 1;
    }
    __syncthreads();
    if (is_last)
        pick256(g_c256, S_SAMPLE, &g_B0, (unsigned*)&g_counters[C_REM], sh);
}

// ---------------------------------------------------------------------------
// hist2: bits[23:16] hist among keys with top byte == B0 (+ fused pick16)
// ---------------------------------------------------------------------------
__global__ void hist2_kernel() {
    __shared__ unsigned sh[256];
    __shared__ unsigned is_last;
    int tid = threadIdx.x;
    sh[tid] = 0;
    if (tid == 0) is_last = 0;
    __syncthreads();
    unsigned b0 = g_B0;
    int stride = gridDim.x * blockDim.x;
    for (int i = blockIdx.x * blockDim.x + tid; i < N_NODES; i += stride) {
        unsigned k = g_keys[i];
        if ((k >> 24) == b0) atomicAdd(&sh[(k >> 16) & 255u], 1u);
    }
    __syncthreads();
    if (sh[tid]) atomicAdd(&g_m256[tid], sh[tid]);
    __threadfence();
    __syncthreads();
    if (tid == 0) {
        unsigned old = atomicAdd(&g_done[1], 1u);
        if (old == gridDim.x - 1) is_last = 1;
    }
    __syncthreads();
    if (is_last) {
        __shared__ unsigned sbin, srem;
        pick256(g_m256, (unsigned)g_counters[C_REM], &sbin, &srem, sh);
        if (tid == 0) {
            g_P16 = (g_B0 << 8) | sbin;
            g_counters[C_REM] = (int)srem;
        }
    }
}

// ---------------------------------------------------------------------------
// flag: classification only (measured 8us); sel->1, others 0
// ---------------------------------------------------------------------------
__global__ void flag_kernel() {
    __shared__ int s_wsel[8], s_weq[8];
    __shared__ int s_osel[8], s_oeq[8];
    __shared__ int s_bsel, s_beq;
    int tid = threadIdx.x;
    int wid = tid >> 5;
    int lane = tid & 31;
    int i = blockIdx.x * blockDim.x + tid;
    bool valid = (i < N_NODES);
    unsigned k = valid ? g_keys[i] : 0u;
    unsigned p = k >> 16;
    unsigned P = g_P16;
    bool sel = valid && (p > P);
    bool eq = valid && (p == P);
    if (valid) g_flag[i] = sel ? 1 : 0;

    unsigned mSel = __ballot_sync(0xFFFFFFFFu, sel);
    unsigned mEq = __ballot_sync(0xFFFFFFFFu, eq);
    if (lane == 0) { s_wsel[wid] = __popc(mSel); s_weq[wid] = __popc(mEq); }
    __syncthreads();
    if (tid == 0) {
        int accS = 0, accE = 0;
#pragma unroll
        for (int wdx = 0; wdx < 8; wdx++) {
            s_osel[wdx] = accS; accS += s_wsel[wdx];
            s_oeq[wdx] = accE; accE += s_weq[wdx];
        }
        s_bsel = accS ? atomicAdd(&g_counters[C_SEL], accS) : 0;
        s_beq = accE ? atomicAdd(&g_counters[C_EQ], accE) : 0;
    }
    __syncthreads();
    unsigned lt = (1u << lane) - 1u;
    if (sel) {
        int pos = s_bsel + s_osel[wid] + __popc(mSel & lt);
        if (pos < S_SAMPLE + M_TILE) g_sel[pos] = i;
    }
    if (eq) {
        int pos = s_beq + s_oeq[wid] + __popc(mEq & lt);
        if (pos < EQCAP) g_eqPair[pos] = make_uint2(k, (unsigned)i);
    }
}

// ---------------------------------------------------------------------------
// eq_resolve: single block; exact T32 + winner selection (winners flag=1,
// losers keep flag=0 -> zeroed by the fused kernel's zero role)
// ---------------------------------------------------------------------------
__global__ void eq_resolve_kernel() {
    __shared__ unsigned hist[256];
    __shared__ unsigned suf[256];
    __shared__ unsigned sb, sneed;
    __shared__ int tie_idx[64];
    __shared__ unsigned tie_cnt;
    int t = threadIdx.x;
    int n = g_counters[C_EQ];
    if (n > EQCAP) n = EQCAP;
    unsigned d = (unsigned)g_counters[C_REM];

    hist[t] = 0;
    if (t == 0) tie_cnt = 0;
    __syncthreads();
    for (int j = t; j < n; j += 256)
        atomicAdd(&hist[(g_eqPair[j].x >> 8) & 255u], 1u);
    __syncthreads();
    pick256(hist, d, &sb, &sneed, suf);
    __syncthreads();
    unsigned b2 = sb, need3 = sneed;

    hist[t] = 0;
    __syncthreads();
    for (int j = t; j < n; j += 256) {
        unsigned k = g_eqPair[j].x;
        if (((k >> 8) & 255u) == b2) atomicAdd(&hist[k & 255u], 1u);
    }
    __syncthreads();
    pick256(hist, need3, &sb, &sneed, suf);
    __syncthreads();
    unsigned T32 = (g_P16 << 16) | (b2 << 8) | sb;
    unsigned ties_needed = sneed;

    for (int j = t; j < n; j += 256) {
        uint2 pr = g_eqPair[j];
        if (pr.x > T32) {
            g_flag[pr.y] = 1;
            int q = atomicAdd(&g_counters[C_SEL], 1);
            if (q < S_SAMPLE + M_TILE) g_sel[q] = (int)pr.y;
        } else if (pr.x == T32) {
            unsigned e = atomicAdd(&tie_cnt, 1u);
            if (e < 64) tie_idx[e] = (int)pr.y;
        }
    }
    __syncthreads();
    int m = (tie_cnt < 64u) ? (int)tie_cnt : 64;
    if (t < m) {
        int idx = tie_idx[t];
        int rank = 0;
        for (int j = 0; j < m; j++) rank += (tie_idx[j] < idx) ? 1 : 0;
        if (rank < (int)ties_needed) {
            g_flag[idx] = 1;
            int q = atomicAdd(&g_counters[C_SEL], 1);
            if (q < S_SAMPLE + M_TILE) g_sel[q] = idx;
        }
    }
}

// ---------------------------------------------------------------------------
// fused GEMM + zero. Low static smem (~22KB) so zero-role occupancy stays
// full. 1:1 interleave for the first 2*NZERO bids; remainder gemm.
// ---------------------------------------------------------------------------
#define A_STRIDE 40    // halves; conflict-free
#define B_STRIDE 264   // halves; conflict-free

__device__ __forceinline__ uint32_t smem_u32(const void* p) {
    uint32_t a;
    asm("{ .reg .u64 t; cvta.to.shared.u64 t, %1; cvt.u32.u64 %0, t; }"
        : "=r"(a) : "l"(p));
    return a;
}

__global__ void __launch_bounds__(256) fused_kernel(
    const float* __restrict__ x, const float* __restrict__ bias,
    float* __restrict__ out) {
    __shared__ __align__(16) __half As[M_TILE * A_STRIDE];
    __shared__ __align__(16) __half Bs[32 * B_STRIDE];
    __shared__ int rows_s[M_TILE];

    int bid = blockIdx.x;
    int tid = threadIdx.x;
    int wid = tid >> 5;
    int lane = tid & 31;

    int gemm_id;
    if (bid < 2 * NZERO) {
        if (bid & 1) {
            // ---- zero role: rows with flag==0 ----
            int gw = (bid >> 1) * 8 + wid;   // 8192 warps total
            float4 z = make_float4(0.f, 0.f, 0.f, 0.f);
            for (int row = gw; row < N_NODES; row += NZERO * 8) {
                if (!g_flag[row]) {
                    float4* p = (float4*)(out + (size_t)row * OUT_C);
                    p[lane] = z;
                    p[lane + 32] = z;
                }
            }
            return;
        }
        gemm_id = bid >> 1;
    } else {
        gemm_id = NZERO + (bid - 2 * NZERO);
    }

    // ---- gemm role ----
    int r0 = gemm_id * M_TILE;
    if (tid < M_TILE) {
        int rr = r0 + tid;
        rows_s[tid] = g_sel[(rr < S_SAMPLE) ? rr : r0];
    }
    __syncthreads();

    int m_half = wid & 1;
    int n_quad = wid >> 1;

    float acc[2][8][4];
#pragma unroll
    for (int mt = 0; mt < 2; mt++)
#pragma unroll
        for (int nt = 0; nt < 8; nt++)
#pragma unroll
            for (int q = 0; q < 4; q++) acc[mt][nt][q] = 0.f;

    int a_row = tid >> 2;
    int a_part = (tid & 3) * 8;
    int b_krow = tid >> 3;
    int b_seg = (tid & 7) * 32;

    const uint32_t As_base = smem_u32(As);
    const uint32_t Bs_base = smem_u32(Bs);
    const float4* a_src = (const float4*)(x + (size_t)rows_s[a_row] * IN_C + a_part);

    // prefetch chunk 0
    float4 pa0 = a_src[0];
    float4 pa1 = a_src[1];
    const uint4* b_src0 = (const uint4*)&g_wh[b_krow * 128 + b_seg / 2];
    uint4 pb0 = b_src0[0], pb1 = b_src0[1], pb2 = b_src0[2], pb3 = b_src0[3];

    for (int kc = 0; kc < 8; kc++) {
        {
            __half2 h0 = __floats2half2_rn(pa0.x, pa0.y);
            __half2 h1 = __floats2half2_rn(pa0.z, pa0.w);
            __half2 h2 = __floats2half2_rn(pa1.x, pa1.y);
            __half2 h3 = __floats2half2_rn(pa1.z, pa1.w);
            unsigned* dst = (unsigned*)&As[a_row * A_STRIDE + a_part];
            dst[0] = *(unsigned*)&h0;
            dst[1] = *(unsigned*)&h1;
            dst[2] = *(unsigned*)&h2;
            dst[3] = *(unsigned*)&h3;
            uint4* bdst = (uint4*)&Bs[b_krow * B_STRIDE + b_seg];
            bdst[0] = pb0; bdst[1] = pb1; bdst[2] = pb2; bdst[3] = pb3;
        }
        __syncthreads();

        if (kc < 7) {
            int k0n = (kc + 1) * 32;
            const float4* an = (const float4*)((const float*)a_src + k0n);
            pa0 = an[0];
            pa1 = an[1];
            const uint4* bn = (const uint4*)&g_wh[(k0n + b_krow) * 128 + b_seg / 2];
            pb0 = bn[0]; pb1 = bn[1]; pb2 = bn[2]; pb3 = bn[3];
        }

#pragma unroll
        for (int ks = 0; ks < 2; ks++) {
            uint32_t af[2][4];
#pragma unroll
            for (int mt = 0; mt < 2; mt++) {
                int row = m_half * 32 + mt * 16 + (lane & 15);
                int col = ks * 16 + (lane >> 4) * 8;
                uint32_t addr = As_base + (row * A_STRIDE + col) * 2;
                asm volatile(
                    "ldmatrix.sync.aligned.m8n8.x4.shared.b16 {%0,%1,%2,%3}, [%4];"
                    : "=r"(af[mt][0]), "=r"(af[mt][1]),
                      "=r"(af[mt][2]), "=r"(af[mt][3]) : "r"(addr));
            }
            uint32_t bf[8][2];
#pragma unroll
            for (int nt = 0; nt < 8; nt++) {
                int krow = ks * 16 + (lane & 15);
                int ncol = n_quad * 64 + nt * 8;
                uint32_t addr = Bs_base + (krow * B_STRIDE + ncol) * 2;
                asm volatile(
                    "ldmatrix.sync.aligned.m8n8.x2.trans.shared.b16 {%0,%1}, [%2];"
                    : "=r"(bf[nt][0]), "=r"(bf[nt][1]) : "r"(addr));
            }
#pragma unroll
            for (int mt = 0; mt < 2; mt++)
#pragma unroll
                for (int nt = 0; nt < 8; nt++) {
                    asm volatile(
                        "mma.sync.aligned.m16n8k16.row.col.f32.f16.f16.f32 "
                        "{%0,%1,%2,%3}, {%4,%5,%6,%7}, {%8,%9}, {%0,%1,%2,%3};"
                        : "+f"(acc[mt][nt][0]), "+f"(acc[mt][nt][1]),
                          "+f"(acc[mt][nt][2]), "+f"(acc[mt][nt][3])
                        : "r"(af[mt][0]), "r"(af[mt][1]),
                          "r"(af[mt][2]), "r"(af[mt][3]),
                          "r"(bf[nt][0]), "r"(bf[nt][1]));
                }
        }
        if (kc < 7) __syncthreads();
    }

    const float scale = 5.0f;
    int qr = lane >> 2;
    int qc = (lane & 3) * 2;
#pragma unroll
    for (int mt = 0; mt < 2; mt++) {
        int lrow_lo = m_half * 32 + mt * 16 + qr;
        int g_lo = rows_s[lrow_lo];
        int g_hi = rows_s[lrow_lo + 8];
        float* row_lo = out + (size_t)g_lo * OUT_C;
        float* row_hi = out + (size_t)g_hi * OUT_C;
#pragma unroll
        for (int nt = 0; nt < 8; nt++) {
            int col = n_quad * 64 + nt * 8 + qc;
            float b0 = bias[col], b1 = bias[col + 1];
            *(float2*)(row_lo + col) = make_float2(
                (acc[mt][nt][0] + b0) * scale, (acc[mt][nt][1] + b1) * scale);
            *(float2*)(row_hi + col) = make_float2(
                (acc[mt][nt][2] + b0) * scale, (acc[mt][nt][3] + b1) * scale);
        }
    }
}

// ---------------------------------------------------------------------------
// Launch
// ---------------------------------------------------------------------------
extern "C" void kernel_launch(void* const* d_in, const int* in_sizes, int n_in,
                              void* d_out, int out_size) {
    const float* x = nullptr;
    const float* w = nullptr;
    const float* bias = nullptr;
    const float* imp = nullptr;
    for (int i = 0; i < n_in; i++) {
        switch (in_sizes[i]) {
            case 128000000: x = (const float*)d_in[i]; break;
            case 65536:     w = (const float*)d_in[i]; break;
            case 256:       bias = (const float*)d_in[i]; break;
            case 500000:    imp = (const float*)d_in[i]; break;
            default: break;  // edge_index unused
        }
    }
    float* out = (float*)d_out;
    (void)out_size;

    prep_kernel<<<128, 256>>>(w);
    score_kernel<<<(N_NODES + 255) / 256, 256>>>(imp);
    hist2_kernel<<<512, 256>>>();
    flag_kernel<<<(N_NODES + 255) / 256, 256>>>();
    eq_resolve_kernel<<<1, 256>>>();
    fused_kernel<<<NTOT, 256>>>(x, bias, out);
}

// round 13
// speedup vs baseline: 1.1907x; 1.1907x over previous
#include <cuda_runtime.h>
#include <cuda_fp16.h>
#include <cstdint>

// ---------------------------------------------------------------------------
// Problem constants
// ---------------------------------------------------------------------------
#define N_NODES 500000
#define S_SAMPLE 100000
#define EQCAP 32768
#define OUT_C 256
#define IN_C 256
#define M_TILE 64
#define NBLK ((S_SAMPLE + M_TILE - 1) / M_TILE)   // 1563

// libdevice accurate log (immune to fast-math logf substitution)
extern "C" __device__ float __nv_logf(float);

// ---------------------------------------------------------------------------
// Device scratch
// ---------------------------------------------------------------------------
__device__ unsigned g_keys[N_NODES];
__device__ unsigned char g_flag[N_NODES];   // only eq rows use this
__device__ int g_sel[S_SAMPLE + M_TILE];
__device__ uint2 g_eqPair[EQCAP];           // (key, idx)
__device__ unsigned g_c256[256];
__device__ unsigned g_m256[256];
__device__ unsigned g_B0;
__device__ unsigned g_P16;
__device__ int g_counters[4];
__device__ unsigned g_done[2];
__device__ volatile unsigned g_eqDone;
__device__ unsigned g_wh[32768];            // w as f16 pairs, [k][n]
#define C_SEL 0
#define C_EQ 1
#define C_REM 2

// ---------------------------------------------------------------------------
// Threefry-2x32, partitionable: x0=0, x1=i, key=(0,42); draw = out0 ^ out1
// ---------------------------------------------------------------------------
__device__ __forceinline__ unsigned rotl32(unsigned x, int r) {
    return (x << r) | (x >> (32 - r));
}
__device__ __forceinline__ unsigned threefry_bits(unsigned i) {
    const unsigned ks0 = 0u, ks1 = 42u;
    const unsigned ks2 = 0x1BD11BDAu ^ ks0 ^ ks1;
    unsigned x0 = 0u + ks0;
    unsigned x1 = i + ks1;
#define TF_R4(a, b, c, d)                                   \
    x0 += x1; x1 = rotl32(x1, a); x1 ^= x0;                 \
    x0 += x1; x1 = rotl32(x1, b); x1 ^= x0;                 \
    x0 += x1; x1 = rotl32(x1, c); x1 ^= x0;                 \
    x0 += x1; x1 = rotl32(x1, d); x1 ^= x0;
    TF_R4(13, 15, 26, 6)  x0 += ks1; x1 += ks2 + 1u;
    TF_R4(17, 29, 16, 24) x0 += ks2; x1 += ks0 + 2u;
    TF_R4(13, 15, 26, 6)  x0 += ks0; x1 += ks1 + 3u;
    TF_R4(17, 29, 16, 24) x0 += ks1; x1 += ks2 + 4u;
    TF_R4(13, 15, 26, 6)  x0 += ks2; x1 += ks0 + 5u;
#undef TF_R4
    return x0 ^ x1;
}
__device__ __forceinline__ unsigned f2key(float f) {
    unsigned b = __float_as_uint(f);
    return (b & 0x80000000u) ? ~b : (b | 0x80000000u);
}

// ---------------------------------------------------------------------------
// suffix-scan pick over a 256-bin hist (in-block)
// ---------------------------------------------------------------------------
__device__ void pick256(const unsigned* hist, unsigned need,
                        unsigned* out_bin, unsigned* out_rem, unsigned* suf) {
    int t = threadIdx.x;
    suf[t] = hist[t];
    __syncthreads();
#pragma unroll
    for (int off = 1; off < 256; off <<= 1) {
        unsigned v = (t + off < 256) ? suf[t + off] : 0u;
        __syncthreads();
        suf[t] += v;
        __syncthreads();
    }
    unsigned above = (t < 255) ? suf[t + 1] : 0u;
    if (suf[t] >= need && above < need) {
        *out_bin = (unsigned)t;
        *out_rem = need - above;
        __threadfence();
    }
    __syncthreads();
}

// ---------------------------------------------------------------------------
// prep: zero counters + convert w to f16
// ---------------------------------------------------------------------------
__global__ void prep_kernel(const float* __restrict__ w) {
    int t = blockIdx.x * blockDim.x + threadIdx.x;   // 32768 threads
    if (t < 256) { g_c256[t] = 0; g_m256[t] = 0; }
    if (t < 4) g_counters[t] = 0;
    if (t < 2) g_done[t] = 0;
    float2 v = ((const float2*)w)[t];
    __half2 h = __floats2half2_rn(v.x, v.y);
    g_wh[t] = *(unsigned*)&h;
}

// ---------------------------------------------------------------------------
// score: keys + shared coarse hist (bits[31:24]) + fused pick8 in tail block
// ---------------------------------------------------------------------------
__global__ void score_kernel(const float* __restrict__ imp) {
    __shared__ unsigned sh[256];
    __shared__ unsigned is_last;
    int tid = threadIdx.x;
    sh[tid] = 0;
    if (tid == 0) is_last = 0;
    __syncthreads();
    int i = blockIdx.x * blockDim.x + tid;
    if (i < N_NODES) {
        unsigned bits = threefry_bits((unsigned)i);
        float f = __uint_as_float((bits >> 9) | 0x3F800000u) - 1.0f;
        float u = f + 1.17549435e-38f;
        float g = -__nv_logf(-__nv_logf(u));
        unsigned k = f2key(__nv_logf(imp[i]) + g);
        g_keys[i] = k;
        atomicAdd(&sh[k >> 24], 1u);
    }
    __syncthreads();
    if (sh[tid]) atomicAdd(&g_c256[tid], sh[tid]);
    __threadfence();
    __syncthreads();
    if (tid == 0) {
        unsigned old = atomicAdd(&g_done[0], 1u);
        if (old == gridDim.x - 1) is_last = 1;
    }
    __syncthreads();
    if (is_last)
        pick256(g_c256, S_SAMPLE, &g_B0, (unsigned*)&g_counters[C_REM], sh);
}

// ---------------------------------------------------------------------------
// hist2: bits[23:16] hist among keys with top byte == B0 (+ fused pick16)
// uint4 loads: 4 keys/thread, MLP=4 (500000 = 125000 * 4)
// ---------------------------------------------------------------------------
__global__ void hist2_kernel() {
    __shared__ unsigned sh[256];
    __shared__ unsigned is_last;
    int tid = threadIdx.x;
    sh[tid] = 0;
    if (tid == 0) is_last = 0;
    __syncthreads();
    unsigned b0 = g_B0;
    int j = blockIdx.x * blockDim.x + tid;
    if (j < N_NODES / 4) {
        uint4 kv = ((const uint4*)g_keys)[j];
        if ((kv.x >> 24) == b0) atomicAdd(&sh[(kv.x >> 16) & 255u], 1u);
        if ((kv.y >> 24) == b0) atomicAdd(&sh[(kv.y >> 16) & 255u], 1u);
        if ((kv.z >> 24) == b0) atomicAdd(&sh[(kv.z >> 16) & 255u], 1u);
        if ((kv.w >> 24) == b0) atomicAdd(&sh[(kv.w >> 16) & 255u], 1u);
    }
    __syncthreads();
    if (sh[tid]) atomicAdd(&g_m256[tid], sh[tid]);
    __threadfence();
    __syncthreads();
    if (tid == 0) {
        unsigned old = atomicAdd(&g_done[1], 1u);
        if (old == gridDim.x - 1) is_last = 1;
    }
    __syncthreads();
    if (is_last) {
        __shared__ unsigned sbin, srem;
        pick256(g_m256, (unsigned)g_counters[C_REM], &sbin, &srem, sh);
        if (tid == 0) {
            g_P16 = (g_B0 << 8) | sbin;
            g_counters[C_REM] = (int)srem;
        }
    }
}

// ---------------------------------------------------------------------------
// flagzero: classify + compact sel/eq lists + zero definite-loser rows inline
// (round-11 measured: 62.6us @ 70% HBM)
// ---------------------------------------------------------------------------
__global__ void flagzero_kernel(float* __restrict__ out) {
    __shared__ int s_wsel[8], s_weq[8];
    __shared__ int s_osel[8], s_oeq[8];
    __shared__ int s_bsel, s_beq;
    int tid = threadIdx.x;
    int wid = tid >> 5;
    int lane = tid & 31;
    int i = blockIdx.x * blockDim.x + tid;
    bool valid = (i < N_NODES);
    unsigned k = valid ? g_keys[i] : 0u;
    unsigned p = k >> 16;
    unsigned P = g_P16;
    bool sel = valid && (p > P);
    bool eq = valid && (p == P);
    if (eq) g_flag[i] = 0;

    unsigned mSel = __ballot_sync(0xFFFFFFFFu, sel);
    unsigned mEq = __ballot_sync(0xFFFFFFFFu, eq);
    if (lane == 0) { s_wsel[wid] = __popc(mSel); s_weq[wid] = __popc(mEq); }
    __syncthreads();
    if (tid == 0) {
        int accS = 0, accE = 0;
#pragma unroll
        for (int wdx = 0; wdx < 8; wdx++) {
            s_osel[wdx] = accS; accS += s_wsel[wdx];
            s_oeq[wdx] = accE; accE += s_weq[wdx];
        }
        s_bsel = accS ? atomicAdd(&g_counters[C_SEL], accS) : 0;
        s_beq = accE ? atomicAdd(&g_counters[C_EQ], accE) : 0;
    }
    __syncthreads();
    unsigned lt = (1u << lane) - 1u;
    if (sel) {
        int pos = s_bsel + s_osel[wid] + __popc(mSel & lt);
        if (pos < S_SAMPLE + M_TILE) g_sel[pos] = i;
    }
    if (eq) {
        int pos = s_beq + s_oeq[wid] + __popc(mEq & lt);
        if (pos < EQCAP) g_eqPair[pos] = make_uint2(k, (unsigned)i);
    }

    // zero definite losers (warp-cooperative, one row per iteration)
    unsigned mZero = __ballot_sync(0xFFFFFFFFu, valid && !sel && !eq);
    int rowbase = blockIdx.x * 256 + wid * 32;
    float4 z = make_float4(0.f, 0.f, 0.f, 0.f);
    for (unsigned m = mZero; m; m &= (m - 1)) {
        int r = __ffs(m) - 1;
        float4* pr = (float4*)(out + (size_t)(rowbase + r) * OUT_C);
        pr[lane] = z;
        pr[lane + 32] = z;
    }
}

// ---------------------------------------------------------------------------
// eq_combined: block 0 radix-resolves exact T32 + winner selection;
// all 64 blocks then zero eq-loser rows (block 1..63 spin on done flag).
// ---------------------------------------------------------------------------
__global__ void eq_combined_kernel(float* __restrict__ out) {
    __shared__ unsigned hist[256];
    __shared__ unsigned suf[256];
    __shared__ unsigned sb, sneed;
    __shared__ int tie_idx[64];
    __shared__ unsigned tie_cnt;
    int t = threadIdx.x;
    int n = g_counters[C_EQ];
    if (n > EQCAP) n = EQCAP;

    if (blockIdx.x == 0) {
        unsigned d = (unsigned)g_counters[C_REM];
        hist[t] = 0;
        if (t == 0) tie_cnt = 0;
        __syncthreads();
        for (int j = t; j < n; j += 256)
            atomicAdd(&hist[(g_eqPair[j].x >> 8) & 255u], 1u);
        __syncthreads();
        pick256(hist, d, &sb, &sneed, suf);
        __syncthreads();
        unsigned b2 = sb, need3 = sneed;
        hist[t] = 0;
        __syncthreads();
        for (int j = t; j < n; j += 256) {
            unsigned k = g_eqPair[j].x;
            if (((k >> 8) & 255u) == b2) atomicAdd(&hist[k & 255u], 1u);
        }
        __syncthreads();
        pick256(hist, need3, &sb, &sneed, suf);
        __syncthreads();
        unsigned T32 = (g_P16 << 16) | (b2 << 8) | sb;
        unsigned ties_needed = sneed;

        for (int j = t; j < n; j += 256) {
            uint2 pr = g_eqPair[j];
            if (pr.x > T32) {
                g_flag[pr.y] = 1;
                int q = atomicAdd(&g_counters[C_SEL], 1);
                if (q < S_SAMPLE + M_TILE) g_sel[q] = (int)pr.y;
            } else if (pr.x == T32) {
                unsigned e = atomicAdd(&tie_cnt, 1u);
                if (e < 64) tie_idx[e] = (int)pr.y;
            }
        }
        __syncthreads();
        int m = (tie_cnt < 64u) ? (int)tie_cnt : 64;
        if (t < m) {
            int idx = tie_idx[t];
            int rank = 0;
            for (int j = 0; j < m; j++) rank += (tie_idx[j] < idx) ? 1 : 0;
            if (rank < (int)ties_needed) {
                g_flag[idx] = 1;
                int q = atomicAdd(&g_counters[C_SEL], 1);
                if (q < S_SAMPLE + M_TILE) g_sel[q] = idx;
            }
        }
        __threadfence();
        __syncthreads();
        if (t == 0) g_eqDone = 1;
        __syncthreads();
    } else {
        if (t == 0) {
            while (g_eqDone == 0) { __nanosleep(64); }
        }
        __syncthreads();
    }

    // all 64 blocks: zero eq losers (flag still 0)
    int lane = t & 31;
    int gw = blockIdx.x * 8 + (t >> 5);
    float4 z = make_float4(0.f, 0.f, 0.f, 0.f);
    for (int base = gw * 32; base < n; base += 512 * 32) {
        int j = base + lane;
        int idx = -1;
        bool loser = false;
        if (j < n) {
            idx = (int)g_eqPair[j].y;
            loser = (g_flag[idx] == 0);
        }
        unsigned m = __ballot_sync(0xFFFFFFFFu, loser);
        while (m) {
            int r = __ffs(m) - 1;
            m &= (m - 1);
            int row = __shfl_sync(0xFFFFFFFFu, idx, r);
            float4* pr = (float4*)(out + (size_t)row * OUT_C);
            pr[lane] = z;
            pr[lane + 32] = z;
        }
    }
}

// ---------------------------------------------------------------------------
// HMMA GEMM: reg-prefetch pipeline + DOUBLE-BUFFERED smem (1 sync/chunk).
// M=64 gathered rows x N=256, K=256 in 32-chunks; 8 warps x (2x8) m16n8k16.
// ---------------------------------------------------------------------------
#define A_STRIDE 40    // halves; conflict-free
#define B_STRIDE 264   // halves; conflict-free
#define AS_HALF (M_TILE * A_STRIDE)      // 2560 halves = 5120 B
#define BS_HALF (32 * B_STRIDE)          // 8448 halves = 16896 B

__device__ __forceinline__ uint32_t smem_u32(const void* p) {
    uint32_t a;
    asm("{ .reg .u64 t; cvta.to.shared.u64 t, %1; cvt.u32.u64 %0, t; }"
        : "=r"(a) : "l"(p));
    return a;
}

__global__ void __launch_bounds__(256) gemm_kernel(
    const float* __restrict__ x, const float* __restrict__ bias,
    float* __restrict__ out) {
    __shared__ __align__(16) __half As[2][AS_HALF];   // 10240 B
    __shared__ __align__(16) __half Bs[2][BS_HALF];   // 33792 B
    __shared__ int rows_s[M_TILE];

    int tid = threadIdx.x;
    int wid = tid >> 5;
    int lane = tid & 31;
    int r0 = blockIdx.x * M_TILE;

    if (tid < M_TILE) {
        int rr = r0 + tid;
        rows_s[tid] = g_sel[(rr < S_SAMPLE) ? rr : r0];
    }
    __syncthreads();

    int m_half = wid & 1;
    int n_quad = wid >> 1;

    float acc[2][8][4];
#pragma unroll
    for (int mt = 0; mt < 2; mt++)
#pragma unroll
        for (int nt = 0; nt < 8; nt++)
#pragma unroll
            for (int q = 0; q < 4; q++) acc[mt][nt][q] = 0.f;

    int a_row = tid >> 2;
    int a_part = (tid & 3) * 8;
    int b_krow = tid >> 3;
    int b_seg = (tid & 7) * 32;

    const uint32_t As_base = smem_u32(As);
    const uint32_t Bs_base = smem_u32(Bs);
    const float4* a_src = (const float4*)(x + (size_t)rows_s[a_row] * IN_C + a_part);

    // prefetch chunk 0
    float4 pa0 = a_src[0];
    float4 pa1 = a_src[1];
    const uint4* b_src0 = (const uint4*)&g_wh[b_krow * 128 + b_seg / 2];
    uint4 pb0 = b_src0[0], pb1 = b_src0[1], pb2 = b_src0[2], pb3 = b_src0[3];

    for (int kc = 0; kc < 8; kc++) {
        int buf = kc & 1;
        // store prefetched chunk kc into buffer buf
        {
            __half2 h0 = __floats2half2_rn(pa0.x, pa0.y);
            __half2 h1 = __floats2half2_rn(pa0.z, pa0.w);
            __half2 h2 = __floats2half2_rn(pa1.x, pa1.y);
            __half2 h3 = __floats2half2_rn(pa1.z, pa1.w);
            unsigned* dst = (unsigned*)&As[buf][a_row * A_STRIDE + a_part];
            dst[0] = *(unsigned*)&h0;
            dst[1] = *(unsigned*)&h1;
            dst[2] = *(unsigned*)&h2;
            dst[3] = *(unsigned*)&h3;
            uint4* bdst = (uint4*)&Bs[buf][b_krow * B_STRIDE + b_seg];
            bdst[0] = pb0; bdst[1] = pb1; bdst[2] = pb2; bdst[3] = pb3;
        }
        __syncthreads();   // single barrier per chunk (double buffer)

        // issue loads for chunk kc+1 (hidden under MMA below)
        if (kc < 7) {
            int k0n = (kc + 1) * 32;
            const float4* an = (const float4*)((const float*)a_src + k0n);
            pa0 = an[0];
            pa1 = an[1];
            const uint4* bn = (const uint4*)&g_wh[(k0n + b_krow) * 128 + b_seg / 2];
            pb0 = bn[0]; pb1 = bn[1]; pb2 = bn[2]; pb3 = bn[3];
        }

        uint32_t aBufBase = As_base + buf * (AS_HALF * 2);
        uint32_t bBufBase = Bs_base + buf * (BS_HALF * 2);
#pragma unroll
        for (int ks = 0; ks < 2; ks++) {
            uint32_t af[2][4];
#pragma unroll
            for (int mt = 0; mt < 2; mt++) {
                int row = m_half * 32 + mt * 16 + (lane & 15);
                int col = ks * 16 + (lane >> 4) * 8;
                uint32_t addr = aBufBase + (row * A_STRIDE + col) * 2;
                asm volatile(
                    "ldmatrix.sync.aligned.m8n8.x4.shared.b16 {%0,%1,%2,%3}, [%4];"
                    : "=r"(af[mt][0]), "=r"(af[mt][1]),
                      "=r"(af[mt][2]), "=r"(af[mt][3]) : "r"(addr));
            }
            uint32_t bf[8][2];
#pragma unroll
            for (int nt = 0; nt < 8; nt++) {
                int krow = ks * 16 + (lane & 15);
                int ncol = n_quad * 64 + nt * 8;
                uint32_t addr = bBufBase + (krow * B_STRIDE + ncol) * 2;
                asm volatile(
                    "ldmatrix.sync.aligned.m8n8.x2.trans.shared.b16 {%0,%1}, [%2];"
                    : "=r"(bf[nt][0]), "=r"(bf[nt][1]) : "r"(addr));
            }
#pragma unroll
            for (int mt = 0; mt < 2; mt++)
#pragma unroll
                for (int nt = 0; nt < 8; nt++) {
                    asm volatile(
                        "mma.sync.aligned.m16n8k16.row.col.f32.f16.f16.f32 "
                        "{%0,%1,%2,%3}, {%4,%5,%6,%7}, {%8,%9}, {%0,%1,%2,%3};"
                        : "+f"(acc[mt][nt][0]), "+f"(acc[mt][nt][1]),
                          "+f"(acc[mt][nt][2]), "+f"(acc[mt][nt][3])
                        : "r"(af[mt][0]), "r"(af[mt][1]),
                          "r"(af[mt][2]), "r"(af[mt][3]),
                          "r"(bf[nt][0]), "r"(bf[nt][1]));
                }
        }
    }

    const float scale = 5.0f;
    int qr = lane >> 2;
    int qc = (lane & 3) * 2;
#pragma unroll
    for (int mt = 0; mt < 2; mt++) {
        int lrow_lo = m_half * 32 + mt * 16 + qr;
        int g_lo = rows_s[lrow_lo];
        int g_hi = rows_s[lrow_lo + 8];
        float* row_lo = out + (size_t)g_lo * OUT_C;
        float* row_hi = out + (size_t)g_hi * OUT_C;
#pragma unroll
        for (int nt = 0; nt < 8; nt++) {
            int col = n_quad * 64 + nt * 8 + qc;
            float b0 = bias[col], b1 = bias[col + 1];
            *(float2*)(row_lo + col) = make_float2(
                (acc[mt][nt][0] + b0) * scale, (acc[mt][nt][1] + b1) * scale);
            *(float2*)(row_hi + col) = make_float2(
                (acc[mt][nt][2] + b0) * scale, (acc[mt][nt][3] + b1) * scale);
        }
    }
}

// ---------------------------------------------------------------------------
// Launch
// ---------------------------------------------------------------------------
extern "C" void kernel_launch(void* const* d_in, const int* in_sizes, int n_in,
                              void* d_out, int out_size) {
    const float* x = nullptr;
    const float* w = nullptr;
    const float* bias = nullptr;
    const float* imp = nullptr;
    for (int i = 0; i < n_in; i++) {
        switch (in_sizes[i]) {
            case 128000000: x = (const float*)d_in[i]; break;
            case 65536:     w = (const float*)d_in[i]; break;
            case 256:       bias = (const float*)d_in[i]; break;
            case 500000:    imp = (const float*)d_in[i]; break;
            default: break;  // edge_index unused
        }
    }
    float* out = (float*)d_out;
    (void)out_size;

    prep_kernel<<<128, 256>>>(w);
    score_kernel<<<(N_NODES + 255) / 256, 256>>>(imp);
    hist2_kernel<<<(N_NODES / 4 + 255) / 256, 256>>>();
    flagzero_kernel<<<(N_NODES + 255) / 256, 256>>>(out);
    eq_combined_kernel<<<64, 256>>>(out);
    gemm_kernel<<<NBLK, 256>>>(x, bias, out);
}

// round 14
// speedup vs baseline: 1.3845x; 1.1628x over previous
#include <cuda_runtime.h>
#include <cuda_fp16.h>
#include <cstdint>

// ---------------------------------------------------------------------------
// Problem constants
// ---------------------------------------------------------------------------
#define N_NODES 500000
#define S_SAMPLE 100000
#define EQCAP 32768
#define OUT_C 256
#define IN_C 256
#define M_TILE 64
#define NBLK ((S_SAMPLE + M_TILE - 1) / M_TILE)   // 1563
#define ZROWS 320                                  // rows zero-checked per block
#define ZCHUNK 40                                  // per k-chunk

// libdevice accurate log (immune to fast-math logf substitution)
extern "C" __device__ float __nv_logf(float);

// ---------------------------------------------------------------------------
// Device scratch
// ---------------------------------------------------------------------------
__device__ unsigned g_keys[N_NODES];
__device__ unsigned char g_flag[N_NODES];   // 1 = row written by gemm
__device__ int g_sel[S_SAMPLE + M_TILE];
__device__ uint2 g_eqPair[EQCAP];           // (key, idx)
__device__ unsigned g_c256[256];
__device__ unsigned g_m256[256];
__device__ unsigned g_B0;
__device__ unsigned g_P16;
__device__ int g_counters[4];
__device__ unsigned g_done[2];
__device__ unsigned g_wh[32768];            // w as f16 pairs, [k][n]
#define C_SEL 0
#define C_EQ 1
#define C_REM 2

// ---------------------------------------------------------------------------
// Threefry-2x32, partitionable: x0=0, x1=i, key=(0,42); draw = out0 ^ out1
// ---------------------------------------------------------------------------
__device__ __forceinline__ unsigned rotl32(unsigned x, int r) {
    return (x << r) | (x >> (32 - r));
}
__device__ __forceinline__ unsigned threefry_bits(unsigned i) {
    const unsigned ks0 = 0u, ks1 = 42u;
    const unsigned ks2 = 0x1BD11BDAu ^ ks0 ^ ks1;
    unsigned x0 = 0u + ks0;
    unsigned x1 = i + ks1;
#define TF_R4(a, b, c, d)                                   \
    x0 += x1; x1 = rotl32(x1, a); x1 ^= x0;                 \
    x0 += x1; x1 = rotl32(x1, b); x1 ^= x0;                 \
    x0 += x1; x1 = rotl32(x1, c); x1 ^= x0;                 \
    x0 += x1; x1 = rotl32(x1, d); x1 ^= x0;
    TF_R4(13, 15, 26, 6)  x0 += ks1; x1 += ks2 + 1u;
    TF_R4(17, 29, 16, 24) x0 += ks2; x1 += ks0 + 2u;
    TF_R4(13, 15, 26, 6)  x0 += ks0; x1 += ks1 + 3u;
    TF_R4(17, 29, 16, 24) x0 += ks1; x1 += ks2 + 4u;
    TF_R4(13, 15, 26, 6)  x0 += ks2; x1 += ks0 + 5u;
#undef TF_R4
    return x0 ^ x1;
}
__device__ __forceinline__ unsigned f2key(float f) {
    unsigned b = __float_as_uint(f);
    return (b & 0x80000000u) ? ~b : (b | 0x80000000u);
}

// ---------------------------------------------------------------------------
// suffix-scan pick over a 256-bin hist (in-block)
// ---------------------------------------------------------------------------
__device__ void pick256(const unsigned* hist, unsigned need,
                        unsigned* out_bin, unsigned* out_rem, unsigned* suf) {
    int t = threadIdx.x;
    suf[t] = hist[t];
    __syncthreads();
#pragma unroll
    for (int off = 1; off < 256; off <<= 1) {
        unsigned v = (t + off < 256) ? suf[t + off] : 0u;
        __syncthreads();
        suf[t] += v;
        __syncthreads();
    }
    unsigned above = (t < 255) ? suf[t + 1] : 0u;
    if (suf[t] >= need && above < need) {
        *out_bin = (unsigned)t;
        *out_rem = need - above;
        __threadfence();
    }
    __syncthreads();
}

// ---------------------------------------------------------------------------
// prep: zero counters + convert w to f16
// ---------------------------------------------------------------------------
__global__ void prep_kernel(const float* __restrict__ w) {
    int t = blockIdx.x * blockDim.x + threadIdx.x;   // 32768 threads
    if (t < 256) { g_c256[t] = 0; g_m256[t] = 0; }
    if (t < 4) g_counters[t] = 0;
    if (t < 2) g_done[t] = 0;
    float2 v = ((const float2*)w)[t];
    __half2 h = __floats2half2_rn(v.x, v.y);
    g_wh[t] = *(unsigned*)&h;
}

// ---------------------------------------------------------------------------
// score: keys + shared coarse hist (bits[31:24]) + fused pick8 in tail block
// ---------------------------------------------------------------------------
__global__ void score_kernel(const float* __restrict__ imp) {
    __shared__ unsigned sh[256];
    __shared__ unsigned is_last;
    int tid = threadIdx.x;
    sh[tid] = 0;
    if (tid == 0) is_last = 0;
    __syncthreads();
    int i = blockIdx.x * blockDim.x + tid;
    if (i < N_NODES) {
        unsigned bits = threefry_bits((unsigned)i);
        float f = __uint_as_float((bits >> 9) | 0x3F800000u) - 1.0f;
        float u = f + 1.17549435e-38f;
        float g = -__nv_logf(-__nv_logf(u));
        unsigned k = f2key(__nv_logf(imp[i]) + g);
        g_keys[i] = k;
        atomicAdd(&sh[k >> 24], 1u);
    }
    __syncthreads();
    if (sh[tid]) atomicAdd(&g_c256[tid], sh[tid]);
    __threadfence();
    __syncthreads();
    if (tid == 0) {
        unsigned old = atomicAdd(&g_done[0], 1u);
        if (old == gridDim.x - 1) is_last = 1;
    }
    __syncthreads();
    if (is_last)
        pick256(g_c256, S_SAMPLE, &g_B0, (unsigned*)&g_counters[C_REM], sh);
}

// ---------------------------------------------------------------------------
// hist2: bits[23:16] hist among keys with top byte == B0 (+ fused pick16)
// ---------------------------------------------------------------------------
__global__ void hist2_kernel() {
    __shared__ unsigned sh[256];
    __shared__ unsigned is_last;
    int tid = threadIdx.x;
    sh[tid] = 0;
    if (tid == 0) is_last = 0;
    __syncthreads();
    unsigned b0 = g_B0;
    int j = blockIdx.x * blockDim.x + tid;
    if (j < N_NODES / 4) {
        uint4 kv = ((const uint4*)g_keys)[j];
        if ((kv.x >> 24) == b0) atomicAdd(&sh[(kv.x >> 16) & 255u], 1u);
        if ((kv.y >> 24) == b0) atomicAdd(&sh[(kv.y >> 16) & 255u], 1u);
        if ((kv.z >> 24) == b0) atomicAdd(&sh[(kv.z >> 16) & 255u], 1u);
        if ((kv.w >> 24) == b0) atomicAdd(&sh[(kv.w >> 16) & 255u], 1u);
    }
    __syncthreads();
    if (sh[tid]) atomicAdd(&g_m256[tid], sh[tid]);
    __threadfence();
    __syncthreads();
    if (tid == 0) {
        unsigned old = atomicAdd(&g_done[1], 1u);
        if (old == gridDim.x - 1) is_last = 1;
    }
    __syncthreads();
    if (is_last) {
        __shared__ unsigned sbin, srem;
        pick256(g_m256, (unsigned)g_counters[C_REM], &sbin, &srem, sh);
        if (tid == 0) {
            g_P16 = (g_B0 << 8) | sbin;
            g_counters[C_REM] = (int)srem;
        }
    }
}

// ---------------------------------------------------------------------------
// flag: classification only (measured ~8us); sel->1, others->0
// ---------------------------------------------------------------------------
__global__ void flag_kernel() {
    __shared__ int s_wsel[8], s_weq[8];
    __shared__ int s_osel[8], s_oeq[8];
    __shared__ int s_bsel, s_beq;
    int tid = threadIdx.x;
    int wid = tid >> 5;
    int lane = tid & 31;
    int i = blockIdx.x * blockDim.x + tid;
    bool valid = (i < N_NODES);
    unsigned k = valid ? g_keys[i] : 0u;
    unsigned p = k >> 16;
    unsigned P = g_P16;
    bool sel = valid && (p > P);
    bool eq = valid && (p == P);
    if (valid) g_flag[i] = sel ? 1 : 0;

    unsigned mSel = __ballot_sync(0xFFFFFFFFu, sel);
    unsigned mEq = __ballot_sync(0xFFFFFFFFu, eq);
    if (lane == 0) { s_wsel[wid] = __popc(mSel); s_weq[wid] = __popc(mEq); }
    __syncthreads();
    if (tid == 0) {
        int accS = 0, accE = 0;
#pragma unroll
        for (int wdx = 0; wdx < 8; wdx++) {
            s_osel[wdx] = accS; accS += s_wsel[wdx];
            s_oeq[wdx] = accE; accE += s_weq[wdx];
        }
        s_bsel = accS ? atomicAdd(&g_counters[C_SEL], accS) : 0;
        s_beq = accE ? atomicAdd(&g_counters[C_EQ], accE) : 0;
    }
    __syncthreads();
    unsigned lt = (1u << lane) - 1u;
    if (sel) {
        int pos = s_bsel + s_osel[wid] + __popc(mSel & lt);
        if (pos < S_SAMPLE + M_TILE) g_sel[pos] = i;
    }
    if (eq) {
        int pos = s_beq + s_oeq[wid] + __popc(mEq & lt);
        if (pos < EQCAP) g_eqPair[pos] = make_uint2(k, (unsigned)i);
    }
}

// ---------------------------------------------------------------------------
// eq_resolve: single block; exact T32 + winner selection (winners flag=1;
// losers keep flag=0 and are zeroed by the gemm's inline zero pass)
// ---------------------------------------------------------------------------
__global__ void eq_resolve_kernel() {
    __shared__ unsigned hist[256];
    __shared__ unsigned suf[256];
    __shared__ unsigned sb, sneed;
    __shared__ int tie_idx[64];
    __shared__ unsigned tie_cnt;
    int t = threadIdx.x;
    int n = g_counters[C_EQ];
    if (n > EQCAP) n = EQCAP;
    unsigned d = (unsigned)g_counters[C_REM];

    hist[t] = 0;
    if (t == 0) tie_cnt = 0;
    __syncthreads();
    for (int j = t; j < n; j += 256)
        atomicAdd(&hist[(g_eqPair[j].x >> 8) & 255u], 1u);
    __syncthreads();
    pick256(hist, d, &sb, &sneed, suf);
    __syncthreads();
    unsigned b2 = sb, need3 = sneed;

    hist[t] = 0;
    __syncthreads();
    for (int j = t; j < n; j += 256) {
        unsigned k = g_eqPair[j].x;
        if (((k >> 8) & 255u) == b2) atomicAdd(&hist[k & 255u], 1u);
    }
    __syncthreads();
    pick256(hist, need3, &sb, &sneed, suf);
    __syncthreads();
    unsigned T32 = (g_P16 << 16) | (b2 << 8) | sb;
    unsigned ties_needed = sneed;

    for (int j = t; j < n; j += 256) {
        uint2 pr = g_eqPair[j];
        if (pr.x > T32) {
            g_flag[pr.y] = 1;
            int q = atomicAdd(&g_counters[C_SEL], 1);
            if (q < S_SAMPLE + M_TILE) g_sel[q] = (int)pr.y;
        } else if (pr.x == T32) {
            unsigned e = atomicAdd(&tie_cnt, 1u);
            if (e < 64) tie_idx[e] = (int)pr.y;
        }
    }
    __syncthreads();
    int m = (tie_cnt < 64u) ? (int)tie_cnt : 64;
    if (t < m) {
        int idx = tie_idx[t];
        int rank = 0;
        for (int j = 0; j < m; j++) rank += (tie_idx[j] < idx) ? 1 : 0;
        if (rank < (int)ties_needed) {
            g_flag[idx] = 1;
            int q = atomicAdd(&g_counters[C_SEL], 1);
            if (q < S_SAMPLE + M_TILE) g_sel[q] = idx;
        }
    }
}

// ---------------------------------------------------------------------------
// HMMA GEMM with inline loser-zeroing. Tensor pipe is the bottleneck (~16k
// cyc/block of HMMA); each block additionally zeroes a 320-row slice of the
// output (flag==0 rows), 40 rows per k-chunk, as fire-and-forget STGs that
// drain under the tensor-bound mainloop. Flags preloaded to smem (no stalls).
// ---------------------------------------------------------------------------
#define A_STRIDE 40    // halves; conflict-free
#define B_STRIDE 264   // halves; conflict-free
#define AS_HALF (M_TILE * A_STRIDE)
#define BS_HALF (32 * B_STRIDE)

__device__ __forceinline__ uint32_t smem_u32(const void* p) {
    uint32_t a;
    asm("{ .reg .u64 t; cvta.to.shared.u64 t, %1; cvt.u32.u64 %0, t; }"
        : "=r"(a) : "l"(p));
    return a;
}

__global__ void __launch_bounds__(256) gemm_kernel(
    const float* __restrict__ x, const float* __restrict__ bias,
    float* __restrict__ out) {
    __shared__ __align__(16) __half As[2][AS_HALF];
    __shared__ __align__(16) __half Bs[2][BS_HALF];
    __shared__ int rows_s[M_TILE];
    __shared__ unsigned char zflag[ZROWS];

    int tid = threadIdx.x;
    int wid = tid >> 5;
    int lane = tid & 31;
    int r0 = blockIdx.x * M_TILE;
    int z0 = blockIdx.x * ZROWS;

    if (tid < M_TILE) {
        int rr = r0 + tid;
        rows_s[tid] = g_sel[(rr < S_SAMPLE) ? rr : r0];
    }
    // preload this block's zero-slice flags into smem
    {
        int zr = z0 + tid;
        zflag[tid] = (zr < N_NODES) ? g_flag[zr] : 1;
        if (tid < ZROWS - 256) {
            int zr2 = z0 + 256 + tid;
            zflag[256 + tid] = (zr2 < N_NODES) ? g_flag[zr2] : 1;
        }
    }
    __syncthreads();

    int m_half = wid & 1;
    int n_quad = wid >> 1;

    float acc[2][8][4];
#pragma unroll
    for (int mt = 0; mt < 2; mt++)
#pragma unroll
        for (int nt = 0; nt < 8; nt++)
#pragma unroll
            for (int q = 0; q < 4; q++) acc[mt][nt][q] = 0.f;

    int a_row = tid >> 2;
    int a_part = (tid & 3) * 8;
    int b_krow = tid >> 3;
    int b_seg = (tid & 7) * 32;

    const uint32_t As_base = smem_u32(As);
    const uint32_t Bs_base = smem_u32(Bs);
    const float4* a_src = (const float4*)(x + (size_t)rows_s[a_row] * IN_C + a_part);

    // prefetch chunk 0
    float4 pa0 = a_src[0];
    float4 pa1 = a_src[1];
    const uint4* b_src0 = (const uint4*)&g_wh[b_krow * 128 + b_seg / 2];
    uint4 pb0 = b_src0[0], pb1 = b_src0[1], pb2 = b_src0[2], pb3 = b_src0[3];

    const float4 z4 = make_float4(0.f, 0.f, 0.f, 0.f);

    for (int kc = 0; kc < 8; kc++) {
        int buf = kc & 1;
        {
            __half2 h0 = __floats2half2_rn(pa0.x, pa0.y);
            __half2 h1 = __floats2half2_rn(pa0.z, pa0.w);
            __half2 h2 = __floats2half2_rn(pa1.x, pa1.y);
            __half2 h3 = __floats2half2_rn(pa1.z, pa1.w);
            unsigned* dst = (unsigned*)&As[buf][a_row * A_STRIDE + a_part];
            dst[0] = *(unsigned*)&h0;
            dst[1] = *(unsigned*)&h1;
            dst[2] = *(unsigned*)&h2;
            dst[3] = *(unsigned*)&h3;
            uint4* bdst = (uint4*)&Bs[buf][b_krow * B_STRIDE + b_seg];
            bdst[0] = pb0; bdst[1] = pb1; bdst[2] = pb2; bdst[3] = pb3;
        }
        __syncthreads();

        if (kc < 7) {
            int k0n = (kc + 1) * 32;
            const float4* an = (const float4*)((const float*)a_src + k0n);
            pa0 = an[0];
            pa1 = an[1];
            const uint4* bn = (const uint4*)&g_wh[(k0n + b_krow) * 128 + b_seg / 2];
            pb0 = bn[0]; pb1 = bn[1]; pb2 = bn[2]; pb3 = bn[3];
        }

        // inline zeroing: 40 rows this chunk, 5 per warp (fire-and-forget)
        {
            int zlocal = kc * ZCHUNK + wid * 5;
#pragma unroll
            for (int zi = 0; zi < 5; zi++) {
                int zl = zlocal + zi;
                int row = z0 + zl;
                if (row < N_NODES && !zflag[zl]) {
                    float4* pr = (float4*)(out + (size_t)row * OUT_C);
                    pr[lane] = z4;
                    pr[lane + 32] = z4;
                }
            }
        }

        uint32_t aBufBase = As_base + buf * (AS_HALF * 2);
        uint32_t bBufBase = Bs_base + buf * (BS_HALF * 2);
#pragma unroll
        for (int ks = 0; ks < 2; ks++) {
            uint32_t af[2][4];
#pragma unroll
            for (int mt = 0; mt < 2; mt++) {
                int row = m_half * 32 + mt * 16 + (lane & 15);
                int col = ks * 16 + (lane >> 4) * 8;
                uint32_t addr = aBufBase + (row * A_STRIDE + col) * 2;
                asm volatile(
                    "ldmatrix.sync.aligned.m8n8.x4.shared.b16 {%0,%1,%2,%3}, [%4];"
                    : "=r"(af[mt][0]), "=r"(af[mt][1]),
                      "=r"(af[mt][2]), "=r"(af[mt][3]) : "r"(addr));
            }
            uint32_t bf[8][2];
#pragma unroll
            for (int nt = 0; nt < 8; nt++) {
                int krow = ks * 16 + (lane & 15);
                int ncol = n_quad * 64 + nt * 8;
                uint32_t addr = bBufBase + (krow * B_STRIDE + ncol) * 2;
                asm volatile(
                    "ldmatrix.sync.aligned.m8n8.x2.trans.shared.b16 {%0,%1}, [%2];"
                    : "=r"(bf[nt][0]), "=r"(bf[nt][1]) : "r"(addr));
            }
#pragma unroll
            for (int mt = 0; mt < 2; mt++)
#pragma unroll
                for (int nt = 0; nt < 8; nt++) {
                    asm volatile(
                        "mma.sync.aligned.m16n8k16.row.col.f32.f16.f16.f32 "
                        "{%0,%1,%2,%3}, {%4,%5,%6,%7}, {%8,%9}, {%0,%1,%2,%3};"
                        : "+f"(acc[mt][nt][0]), "+f"(acc[mt][nt][1]),
                          "+f"(acc[mt][nt][2]), "+f"(acc[mt][nt][3])
                        : "r"(af[mt][0]), "r"(af[mt][1]),
                          "r"(af[mt][2]), "r"(af[mt][3]),
                          "r"(bf[nt][0]), "r"(bf[nt][1]));
                }
        }
    }

    const float scale = 5.0f;
    int qr = lane >> 2;
    int qc = (lane & 3) * 2;
#pragma unroll
    for (int mt = 0; mt < 2; mt++) {
        int lrow_lo = m_half * 32 + mt * 16 + qr;
        int g_lo = rows_s[lrow_lo];
        int g_hi = rows_s[lrow_lo + 8];
        float* row_lo = out + (size_t)g_lo * OUT_C;
        float* row_hi = out + (size_t)g_hi * OUT_C;
#pragma unroll
        for (int nt = 0; nt < 8; nt++) {
            int col = n_quad * 64 + nt * 8 + qc;
            float b0 = bias[col], b1 = bias[col + 1];
            *(float2*)(row_lo + col) = make_float2(
                (acc[mt][nt][0] + b0) * scale, (acc[mt][nt][1] + b1) * scale);
            *(float2*)(row_hi + col) = make_float2(
                (acc[mt][nt][2] + b0) * scale, (acc[mt][nt][3] + b1) * scale);
        }
    }
}

// ---------------------------------------------------------------------------
// Launch
// ---------------------------------------------------------------------------
extern "C" void kernel_launch(void* const* d_in, const int* in_sizes, int n_in,
                              void* d_out, int out_size) {
    const float* x = nullptr;
    const float* w = nullptr;
    const float* bias = nullptr;
    const float* imp = nullptr;
    for (int i = 0; i < n_in; i++) {
        switch (in_sizes[i]) {
            case 128000000: x = (const float*)d_in[i]; break;
            case 65536:     w = (const float*)d_in[i]; break;
            case 256:       bias = (const float*)d_in[i]; break;
            case 500000:    imp = (const float*)d_in[i]; break;
            default: break;  // edge_index unused
        }
    }
    float* out = (float*)d_out;
    (void)out_size;

    prep_kernel<<<128, 256>>>(w);
    score_kernel<<<(N_NODES + 255) / 256, 256>>>(imp);
    hist2_kernel<<<(N_NODES / 4 + 255) / 256, 256>>>();
    flag_kernel<<<(N_NODES + 255) / 256, 256>>>();
    eq_resolve_kernel<<<1, 256>>>();
    gemm_kernel<<<NBLK, 256>>>(x, bias, out);
}

// round 15
// speedup vs baseline: 1.4177x; 1.0239x over previous
#include <cuda_runtime.h>
#include <cuda_fp16.h>
#include <cstdint>

// ---------------------------------------------------------------------------
// Problem constants
// ---------------------------------------------------------------------------
#define N_NODES 500000
#define S_SAMPLE 100000
#define EQCAP 32768
#define OUT_C 256
#define IN_C 256
#define M_TILE 64
#define NBLK ((S_SAMPLE + M_TILE - 1) / M_TILE)   // 1563
#define ZROWS 320
#define ZCHUNK 40

// libdevice accurate log (immune to fast-math logf substitution)
extern "C" __device__ float __nv_logf(float);

// ---------------------------------------------------------------------------
// Device scratch (zero-initialized at load; gemm block 0 re-zeroes the
// counters at the END of each call -> clean state for the next graph replay)
// ---------------------------------------------------------------------------
__device__ unsigned g_keys[N_NODES];
__device__ unsigned char g_flag[N_NODES];   // 1 = row written by gemm
__device__ int g_sel[S_SAMPLE + M_TILE];
__device__ uint2 g_eqPair[EQCAP];           // (key, idx)
__device__ unsigned g_c256[256];
__device__ unsigned g_m256[256];
__device__ unsigned g_B0;
__device__ unsigned g_P16;
__device__ int g_counters[4];
__device__ unsigned g_done[3];
__device__ unsigned g_wh[32768];            // w as f16 pairs, [k][n]
#define C_SEL 0
#define C_EQ 1
#define C_REM 2

// ---------------------------------------------------------------------------
// Threefry-2x32, partitionable: x0=0, x1=i, key=(0,42); draw = out0 ^ out1
// ---------------------------------------------------------------------------
__device__ __forceinline__ unsigned rotl32(unsigned x, int r) {
    return (x << r) | (x >> (32 - r));
}
__device__ __forceinline__ unsigned threefry_bits(unsigned i) {
    const unsigned ks0 = 0u, ks1 = 42u;
    const unsigned ks2 = 0x1BD11BDAu ^ ks0 ^ ks1;
    unsigned x0 = 0u + ks0;
    unsigned x1 = i + ks1;
#define TF_R4(a, b, c, d)                                   \
    x0 += x1; x1 = rotl32(x1, a); x1 ^= x0;                 \
    x0 += x1; x1 = rotl32(x1, b); x1 ^= x0;                 \
    x0 += x1; x1 = rotl32(x1, c); x1 ^= x0;                 \
    x0 += x1; x1 = rotl32(x1, d); x1 ^= x0;
    TF_R4(13, 15, 26, 6)  x0 += ks1; x1 += ks2 + 1u;
    TF_R4(17, 29, 16, 24) x0 += ks2; x1 += ks0 + 2u;
    TF_R4(13, 15, 26, 6)  x0 += ks0; x1 += ks1 + 3u;
    TF_R4(17, 29, 16, 24) x0 += ks1; x1 += ks2 + 4u;
    TF_R4(13, 15, 26, 6)  x0 += ks2; x1 += ks0 + 5u;
#undef TF_R4
    return x0 ^ x1;
}
__device__ __forceinline__ unsigned f2key(float f) {
    unsigned b = __float_as_uint(f);
    return (b & 0x80000000u) ? ~b : (b | 0x80000000u);
}

// ---------------------------------------------------------------------------
// suffix-scan pick over a 256-bin hist (in-block)
// ---------------------------------------------------------------------------
__device__ void pick256(const unsigned* hist, unsigned need,
                        unsigned* out_bin, unsigned* out_rem, unsigned* suf) {
    int t = threadIdx.x;
    suf[t] = hist[t];
    __syncthreads();
#pragma unroll
    for (int off = 1; off < 256; off <<= 1) {
        unsigned v = (t + off < 256) ? suf[t + off] : 0u;
        __syncthreads();
        suf[t] += v;
        __syncthreads();
    }
    unsigned above = (t < 255) ? suf[t + 1] : 0u;
    if (suf[t] >= need && above < need) {
        *out_bin = (unsigned)t;
        *out_rem = need - above;
        __threadfence();
    }
    __syncthreads();
}

// ---------------------------------------------------------------------------
// score: keys + coarse hist + fused pick8 in tail block.
// Blocks 0..127 additionally convert w -> f16 (replaces prep_kernel).
// ---------------------------------------------------------------------------
__global__ void score_kernel(const float* __restrict__ imp,
                             const float* __restrict__ w) {
    __shared__ unsigned sh[256];
    __shared__ unsigned is_last;
    int tid = threadIdx.x;
    sh[tid] = 0;
    if (tid == 0) is_last = 0;
    __syncthreads();
    // fold prep: w conversion by the first 128 blocks
    if (blockIdx.x < 128) {
        int t = blockIdx.x * 256 + tid;
        float2 v = ((const float2*)w)[t];
        __half2 h = __floats2half2_rn(v.x, v.y);
        g_wh[t] = *(unsigned*)&h;
    }
    int i = blockIdx.x * blockDim.x + tid;
    if (i < N_NODES) {
        unsigned bits = threefry_bits((unsigned)i);
        float f = __uint_as_float((bits >> 9) | 0x3F800000u) - 1.0f;
        float u = f + 1.17549435e-38f;
        float g = -__nv_logf(-__nv_logf(u));
        unsigned k = f2key(__nv_logf(imp[i]) + g);
        g_keys[i] = k;
        atomicAdd(&sh[k >> 24], 1u);
    }
    __syncthreads();
    if (sh[tid]) atomicAdd(&g_c256[tid], sh[tid]);
    __threadfence();
    __syncthreads();
    if (tid == 0) {
        unsigned old = atomicAdd(&g_done[0], 1u);
        if (old == gridDim.x - 1) is_last = 1;
    }
    __syncthreads();
    if (is_last)
        pick256(g_c256, S_SAMPLE, &g_B0, (unsigned*)&g_counters[C_REM], sh);
}

// ---------------------------------------------------------------------------
// hist2: bits[23:16] hist among keys with top byte == B0 (+ fused pick16)
// ---------------------------------------------------------------------------
__global__ void hist2_kernel() {
    __shared__ unsigned sh[256];
    __shared__ unsigned is_last;
    int tid = threadIdx.x;
    sh[tid] = 0;
    if (tid == 0) is_last = 0;
    __syncthreads();
    unsigned b0 = g_B0;
    int j = blockIdx.x * blockDim.x + tid;
    if (j < N_NODES / 4) {
        uint4 kv = ((const uint4*)g_keys)[j];
        if ((kv.x >> 24) == b0) atomicAdd(&sh[(kv.x >> 16) & 255u], 1u);
        if ((kv.y >> 24) == b0) atomicAdd(&sh[(kv.y >> 16) & 255u], 1u);
        if ((kv.z >> 24) == b0) atomicAdd(&sh[(kv.z >> 16) & 255u], 1u);
        if ((kv.w >> 24) == b0) atomicAdd(&sh[(kv.w >> 16) & 255u], 1u);
    }
    __syncthreads();
    if (sh[tid]) atomicAdd(&g_m256[tid], sh[tid]);
    __threadfence();
    __syncthreads();
    if (tid == 0) {
        unsigned old = atomicAdd(&g_done[1], 1u);
        if (old == gridDim.x - 1) is_last = 1;
    }
    __syncthreads();
    if (is_last) {
        __shared__ unsigned sbin, srem;
        pick256(g_m256, (unsigned)g_counters[C_REM], &sbin, &srem, sh);
        if (tid == 0) {
            g_P16 = (g_B0 << 8) | sbin;
            g_counters[C_REM] = (int)srem;
        }
    }
}

// ---------------------------------------------------------------------------
// flag: classification + compaction; tail block runs eq_resolve inline.
// ---------------------------------------------------------------------------
__global__ void flag_kernel() {
    __shared__ int s_wsel[8], s_weq[8];
    __shared__ int s_osel[8], s_oeq[8];
    __shared__ int s_bsel, s_beq;
    __shared__ unsigned is_last;
    __shared__ unsigned hist[256];
    __shared__ unsigned suf[256];
    __shared__ unsigned sb, sneed;
    __shared__ int tie_idx[64];
    __shared__ unsigned tie_cnt;

    int tid = threadIdx.x;
    int wid = tid >> 5;
    int lane = tid & 31;
    if (tid == 0) is_last = 0;
    int i = blockIdx.x * blockDim.x + tid;
    bool valid = (i < N_NODES);
    unsigned k = valid ? g_keys[i] : 0u;
    unsigned p = k >> 16;
    unsigned P = g_P16;
    bool sel = valid && (p > P);
    bool eq = valid && (p == P);
    if (valid) g_flag[i] = sel ? 1 : 0;

    unsigned mSel = __ballot_sync(0xFFFFFFFFu, sel);
    unsigned mEq = __ballot_sync(0xFFFFFFFFu, eq);
    if (lane == 0) { s_wsel[wid] = __popc(mSel); s_weq[wid] = __popc(mEq); }
    __syncthreads();
    if (tid == 0) {
        int accS = 0, accE = 0;
#pragma unroll
        for (int wdx = 0; wdx < 8; wdx++) {
            s_osel[wdx] = accS; accS += s_wsel[wdx];
            s_oeq[wdx] = accE; accE += s_weq[wdx];
        }
        s_bsel = accS ? atomicAdd(&g_counters[C_SEL], accS) : 0;
        s_beq = accE ? atomicAdd(&g_counters[C_EQ], accE) : 0;
    }
    __syncthreads();
    unsigned lt = (1u << lane) - 1u;
    if (sel) {
        int pos = s_bsel + s_osel[wid] + __popc(mSel & lt);
        if (pos < S_SAMPLE + M_TILE) g_sel[pos] = i;
    }
    if (eq) {
        int pos = s_beq + s_oeq[wid] + __popc(mEq & lt);
        if (pos < EQCAP) g_eqPair[pos] = make_uint2(k, (unsigned)i);
    }

    // ---- tail block: eq_resolve inline (proven done-counter idiom) ----
    __threadfence();
    __syncthreads();
    if (tid == 0) {
        unsigned old = atomicAdd(&g_done[2], 1u);
        if (old == gridDim.x - 1) is_last = 1;
    }
    __syncthreads();
    if (!is_last) return;

    int t = tid;
    int n = g_counters[C_EQ];
    if (n > EQCAP) n = EQCAP;
    unsigned d = (unsigned)g_counters[C_REM];

    hist[t] = 0;
    if (t == 0) tie_cnt = 0;
    __syncthreads();
    for (int j = t; j < n; j += 256)
        atomicAdd(&hist[(g_eqPair[j].x >> 8) & 255u], 1u);
    __syncthreads();
    pick256(hist, d, &sb, &sneed, suf);
    __syncthreads();
    unsigned b2 = sb, need3 = sneed;

    hist[t] = 0;
    __syncthreads();
    for (int j = t; j < n; j += 256) {
        unsigned kk = g_eqPair[j].x;
        if (((kk >> 8) & 255u) == b2) atomicAdd(&hist[kk & 255u], 1u);
    }
    __syncthreads();
    pick256(hist, need3, &sb, &sneed, suf);
    __syncthreads();
    unsigned T32 = (g_P16 << 16) | (b2 << 8) | sb;
    unsigned ties_needed = sneed;

    for (int j = t; j < n; j += 256) {
        uint2 pr = g_eqPair[j];
        if (pr.x > T32) {
            g_flag[pr.y] = 1;
            int q = atomicAdd(&g_counters[C_SEL], 1);
            if (q < S_SAMPLE + M_TILE) g_sel[q] = (int)pr.y;
        } else if (pr.x == T32) {
            unsigned e = atomicAdd(&tie_cnt, 1u);
            if (e < 64) tie_idx[e] = (int)pr.y;
        }
    }
    __syncthreads();
    int m = (tie_cnt < 64u) ? (int)tie_cnt : 64;
    if (t < m) {
        int idx = tie_idx[t];
        int rank = 0;
        for (int j = 0; j < m; j++) rank += (tie_idx[j] < idx) ? 1 : 0;
        if (rank < (int)ties_needed) {
            g_flag[idx] = 1;
            int q = atomicAdd(&g_counters[C_SEL], 1);
            if (q < S_SAMPLE + M_TILE) g_sel[q] = idx;
        }
    }
}

// ---------------------------------------------------------------------------
// HMMA GEMM with inline loser-zeroing (round-14 measured winner, unchanged)
// + end-of-kernel counter cleanup in block 0 (prep for next graph replay).
// ---------------------------------------------------------------------------
#define A_STRIDE 40
#define B_STRIDE 264
#define AS_HALF (M_TILE * A_STRIDE)
#define BS_HALF (32 * B_STRIDE)

__device__ __forceinline__ uint32_t smem_u32(const void* p) {
    uint32_t a;
    asm("{ .reg .u64 t; cvta.to.shared.u64 t, %1; cvt.u32.u64 %0, t; }"
        : "=r"(a) : "l"(p));
    return a;
}

__global__ void __launch_bounds__(256) gemm_kernel(
    const float* __restrict__ x, const float* __restrict__ bias,
    float* __restrict__ out) {
    __shared__ __align__(16) __half As[2][AS_HALF];
    __shared__ __align__(16) __half Bs[2][BS_HALF];
    __shared__ int rows_s[M_TILE];
    __shared__ unsigned char zflag[ZROWS];

    int tid = threadIdx.x;
    int wid = tid >> 5;
    int lane = tid & 31;
    int r0 = blockIdx.x * M_TILE;
    int z0 = blockIdx.x * ZROWS;

    if (tid < M_TILE) {
        int rr = r0 + tid;
        rows_s[tid] = g_sel[(rr < S_SAMPLE) ? rr : r0];
    }
    {
        int zr = z0 + tid;
        zflag[tid] = (zr < N_NODES) ? g_flag[zr] : 1;
        if (tid < ZROWS - 256) {
            int zr2 = z0 + 256 + tid;
            zflag[256 + tid] = (zr2 < N_NODES) ? g_flag[zr2] : 1;
        }
    }
    __syncthreads();

    int m_half = wid & 1;
    int n_quad = wid >> 1;

    float acc[2][8][4];
#pragma unroll
    for (int mt = 0; mt < 2; mt++)
#pragma unroll
        for (int nt = 0; nt < 8; nt++)
#pragma unroll
            for (int q = 0; q < 4; q++) acc[mt][nt][q] = 0.f;

    int a_row = tid >> 2;
    int a_part = (tid & 3) * 8;
    int b_krow = tid >> 3;
    int b_seg = (tid & 7) * 32;

    const uint32_t As_base = smem_u32(As);
    const uint32_t Bs_base = smem_u32(Bs);
    const float4* a_src = (const float4*)(x + (size_t)rows_s[a_row] * IN_C + a_part);

    float4 pa0 = a_src[0];
    float4 pa1 = a_src[1];
    const uint4* b_src0 = (const uint4*)&g_wh[b_krow * 128 + b_seg / 2];
    uint4 pb0 = b_src0[0], pb1 = b_src0[1], pb2 = b_src0[2], pb3 = b_src0[3];

    const float4 z4 = make_float4(0.f, 0.f, 0.f, 0.f);

    for (int kc = 0; kc < 8; kc++) {
        int buf = kc & 1;
        {
            __half2 h0 = __floats2half2_rn(pa0.x, pa0.y);
            __half2 h1 = __floats2half2_rn(pa0.z, pa0.w);
            __half2 h2 = __floats2half2_rn(pa1.x, pa1.y);
            __half2 h3 = __floats2half2_rn(pa1.z, pa1.w);
            unsigned* dst = (unsigned*)&As[buf][a_row * A_STRIDE + a_part];
            dst[0] = *(unsigned*)&h0;
            dst[1] = *(unsigned*)&h1;
            dst[2] = *(unsigned*)&h2;
            dst[3] = *(unsigned*)&h3;
            uint4* bdst = (uint4*)&Bs[buf][b_krow * B_STRIDE + b_seg];
            bdst[0] = pb0; bdst[1] = pb1; bdst[2] = pb2; bdst[3] = pb3;
        }
        __syncthreads();

        if (kc < 7) {
            int k0n = (kc + 1) * 32;
            const float4* an = (const float4*)((const float*)a_src + k0n);
            pa0 = an[0];
            pa1 = an[1];
            const uint4* bn = (const uint4*)&g_wh[(k0n + b_krow) * 128 + b_seg / 2];
            pb0 = bn[0]; pb1 = bn[1]; pb2 = bn[2]; pb3 = bn[3];
        }

        // inline zeroing: 40 rows this chunk, 5 per warp (fire-and-forget)
        {
            int zlocal = kc * ZCHUNK + wid * 5;
#pragma unroll
            for (int zi = 0; zi < 5; zi++) {
                int zl = zlocal + zi;
                int row = z0 + zl;
                if (row < N_NODES && !zflag[zl]) {
                    float4* pr = (float4*)(out + (size_t)row * OUT_C);
                    pr[lane] = z4;
                    pr[lane + 32] = z4;
                }
            }
        }

        uint32_t aBufBase = As_base + buf * (AS_HALF * 2);
        uint32_t bBufBase = Bs_base + buf * (BS_HALF * 2);
#pragma unroll
        for (int ks = 0; ks < 2; ks++) {
            uint32_t af[2][4];
#pragma unroll
            for (int mt = 0; mt < 2; mt++) {
                int row = m_half * 32 + mt * 16 + (lane & 15);
                int col = ks * 16 + (lane >> 4) * 8;
                uint32_t addr = aBufBase + (row * A_STRIDE + col) * 2;
                asm volatile(
                    "ldmatrix.sync.aligned.m8n8.x4.shared.b16 {%0,%1,%2,%3}, [%4];"
                    : "=r"(af[mt][0]), "=r"(af[mt][1]),
                      "=r"(af[mt][2]), "=r"(af[mt][3]) : "r"(addr));
            }
            uint32_t bf[8][2];
#pragma unroll
            for (int nt = 0; nt < 8; nt++) {
                int krow = ks * 16 + (lane & 15);
                int ncol = n_quad * 64 + nt * 8;
                uint32_t addr = bBufBase + (krow * B_STRIDE + ncol) * 2;
                asm volatile(
                    "ldmatrix.sync.aligned.m8n8.x2.trans.shared.b16 {%0,%1}, [%2];"
                    : "=r"(bf[nt][0]), "=r"(bf[nt][1]) : "r"(addr));
            }
#pragma unroll
            for (int mt = 0; mt < 2; mt++)
#pragma unroll
                for (int nt = 0; nt < 8; nt++) {
                    asm volatile(
                        "mma.sync.aligned.m16n8k16.row.col.f32.f16.f16.f32 "
                        "{%0,%1,%2,%3}, {%4,%5,%6,%7}, {%8,%9}, {%0,%1,%2,%3};"
                        : "+f"(acc[mt][nt][0]), "+f"(acc[mt][nt][1]),
                          "+f"(acc[mt][nt][2]), "+f"(acc[mt][nt][3])
                        : "r"(af[mt][0]), "r"(af[mt][1]),
                          "r"(af[mt][2]), "r"(af[mt][3]),
                          "r"(bf[nt][0]), "r"(bf[nt][1]));
                }
        }
    }

    const float scale = 5.0f;
    int qr = lane >> 2;
    int qc = (lane & 3) * 2;
#pragma unroll
    for (int mt = 0; mt < 2; mt++) {
        int lrow_lo = m_half * 32 + mt * 16 + qr;
        int g_lo = rows_s[lrow_lo];
        int g_hi = rows_s[lrow_lo + 8];
        float* row_lo = out + (size_t)g_lo * OUT_C;
        float* row_hi = out + (size_t)g_hi * OUT_C;
#pragma unroll
        for (int nt = 0; nt < 8; nt++) {
            int col = n_quad * 64 + nt * 8 + qc;
            float b0 = bias[col], b1 = bias[col + 1];
            *(float2*)(row_lo + col) = make_float2(
                (acc[mt][nt][0] + b0) * scale, (acc[mt][nt][1] + b1) * scale);
            *(float2*)(row_hi + col) = make_float2(
                (acc[mt][nt][2] + b0) * scale, (acc[mt][nt][3] + b1) * scale);
        }
    }

    // cleanup for next replay (counters consumed only by earlier kernels)
    if (blockIdx.x == 0) {
        g_c256[tid] = 0;
        g_m256[tid] = 0;
        if (tid < 4) g_counters[tid] = 0;
        if (tid < 3) g_done[tid] = 0;
    }
}

// ---------------------------------------------------------------------------
// Launch (4 kernels)
// ---------------------------------------------------------------------------
extern "C" void kernel_launch(void* const* d_in, const int* in_sizes, int n_in,
                              void* d_out, int out_size) {
    const float* x = nullptr;
    const float* w = nullptr;
    const float* bias = nullptr;
    const float* imp = nullptr;
    for (int i = 0; i < n_in; i++) {
        switch (in_sizes[i]) {
            case 128000000: x = (const float*)d_in[i]; break;
            case 65536:     w = (const float*)d_in[i]; break;
            case 256:       bias = (const float*)d_in[i]; break;
            case 500000:    imp = (const float*)d_in[i]; break;
            default: break;  // edge_index unused
        }
    }
    float* out = (float*)d_out;
    (void)out_size;

    score_kernel<<<(N_NODES + 255) / 256, 256>>>(imp, w);
    hist2_kernel<<<(N_NODES / 4 + 255) / 256, 256>>>();
    flag_kernel<<<(N_NODES + 255) / 256, 256>>>();
    gemm_kernel<<<NBLK, 256>>>(x, bias, out);
}

// round 16
// speedup vs baseline: 1.5084x; 1.0640x over previous
#include <cuda_runtime.h>
#include <cuda_fp16.h>
#include <cstdint>

// ---------------------------------------------------------------------------
// Problem constants
// ---------------------------------------------------------------------------
#define N_NODES 500000
#define S_SAMPLE 100000
#define EQCAP 32768
#define OUT_C 256
#define IN_C 256
#define M_TILE 64
#define NBLK ((S_SAMPLE + M_TILE - 1) / M_TILE)   // 1563
#define NGEMM (2 * NBLK)                          // 3126 (N split in halves)
#define ZROWS 160
#define ZCHUNK 20

// libdevice accurate log (immune to fast-math logf substitution)
extern "C" __device__ float __nv_logf(float);

// ---------------------------------------------------------------------------
// Device scratch (zero-initialized at load; gemm block 0 re-zeroes the
// counters at the END of each call -> clean state for the next graph replay)
// ---------------------------------------------------------------------------
__device__ unsigned g_keys[N_NODES];
__device__ unsigned char g_flag[N_NODES];   // 1 = row written by gemm
__device__ int g_sel[S_SAMPLE + M_TILE];
__device__ uint2 g_eqPair[EQCAP];           // (key, idx)
__device__ unsigned g_c256[256];
__device__ unsigned g_m256[256];
__device__ unsigned g_B0;
__device__ unsigned g_P16;
__device__ int g_counters[4];
__device__ unsigned g_done[3];
__device__ unsigned g_wh[32768];            // w as f16 pairs, [k][n]
#define C_SEL 0
#define C_EQ 1
#define C_REM 2

// ---------------------------------------------------------------------------
// Threefry-2x32, partitionable: x0=0, x1=i, key=(0,42); draw = out0 ^ out1
// ---------------------------------------------------------------------------
__device__ __forceinline__ unsigned rotl32(unsigned x, int r) {
    return (x << r) | (x >> (32 - r));
}
__device__ __forceinline__ unsigned threefry_bits(unsigned i) {
    const unsigned ks0 = 0u, ks1 = 42u;
    const unsigned ks2 = 0x1BD11BDAu ^ ks0 ^ ks1;
    unsigned x0 = 0u + ks0;
    unsigned x1 = i + ks1;
#define TF_R4(a, b, c, d)                                   \
    x0 += x1; x1 = rotl32(x1, a); x1 ^= x0;                 \
    x0 += x1; x1 = rotl32(x1, b); x1 ^= x0;                 \
    x0 += x1; x1 = rotl32(x1, c); x1 ^= x0;                 \
    x0 += x1; x1 = rotl32(x1, d); x1 ^= x0;
    TF_R4(13, 15, 26, 6)  x0 += ks1; x1 += ks2 + 1u;
    TF_R4(17, 29, 16, 24) x0 += ks2; x1 += ks0 + 2u;
    TF_R4(13, 15, 26, 6)  x0 += ks0; x1 += ks1 + 3u;
    TF_R4(17, 29, 16, 24) x0 += ks1; x1 += ks2 + 4u;
    TF_R4(13, 15, 26, 6)  x0 += ks2; x1 += ks0 + 5u;
#undef TF_R4
    return x0 ^ x1;
}
__device__ __forceinline__ unsigned f2key(float f) {
    unsigned b = __float_as_uint(f);
    return (b & 0x80000000u) ? ~b : (b | 0x80000000u);
}

// ---------------------------------------------------------------------------
// suffix-scan pick over a 256-bin hist (in-block)
// ---------------------------------------------------------------------------
__device__ void pick256(const unsigned* hist, unsigned need,
                        unsigned* out_bin, unsigned* out_rem, unsigned* suf) {
    int t = threadIdx.x;
    suf[t] = hist[t];
    __syncthreads();
#pragma unroll
    for (int off = 1; off < 256; off <<= 1) {
        unsigned v = (t + off < 256) ? suf[t + off] : 0u;
        __syncthreads();
        suf[t] += v;
        __syncthreads();
    }
    unsigned above = (t < 255) ? suf[t + 1] : 0u;
    if (suf[t] >= need && above < need) {
        *out_bin = (unsigned)t;
        *out_rem = need - above;
        __threadfence();
    }
    __syncthreads();
}

// ---------------------------------------------------------------------------
// score: keys + coarse hist + fused pick8 in tail block + w conversion
// ---------------------------------------------------------------------------
__global__ void score_kernel(const float* __restrict__ imp,
                             const float* __restrict__ w) {
    __shared__ unsigned sh[256];
    __shared__ unsigned is_last;
    int tid = threadIdx.x;
    sh[tid] = 0;
    if (tid == 0) is_last = 0;
    __syncthreads();
    if (blockIdx.x < 128) {
        int t = blockIdx.x * 256 + tid;
        float2 v = ((const float2*)w)[t];
        __half2 h = __floats2half2_rn(v.x, v.y);
        g_wh[t] = *(unsigned*)&h;
    }
    int i = blockIdx.x * blockDim.x + tid;
    if (i < N_NODES) {
        unsigned bits = threefry_bits((unsigned)i);
        float f = __uint_as_float((bits >> 9) | 0x3F800000u) - 1.0f;
        float u = f + 1.17549435e-38f;
        float g = -__nv_logf(-__nv_logf(u));
        unsigned k = f2key(__nv_logf(imp[i]) + g);
        g_keys[i] = k;
        atomicAdd(&sh[k >> 24], 1u);
    }
    __syncthreads();
    if (sh[tid]) atomicAdd(&g_c256[tid], sh[tid]);
    __threadfence();
    __syncthreads();
    if (tid == 0) {
        unsigned old = atomicAdd(&g_done[0], 1u);
        if (old == gridDim.x - 1) is_last = 1;
    }
    __syncthreads();
    if (is_last)
        pick256(g_c256, S_SAMPLE, &g_B0, (unsigned*)&g_counters[C_REM], sh);
}

// ---------------------------------------------------------------------------
// hist2: bits[23:16] hist among keys with top byte == B0 (+ fused pick16)
// ---------------------------------------------------------------------------
__global__ void hist2_kernel() {
    __shared__ unsigned sh[256];
    __shared__ unsigned is_last;
    int tid = threadIdx.x;
    sh[tid] = 0;
    if (tid == 0) is_last = 0;
    __syncthreads();
    unsigned b0 = g_B0;
    int j = blockIdx.x * blockDim.x + tid;
    if (j < N_NODES / 4) {
        uint4 kv = ((const uint4*)g_keys)[j];
        if ((kv.x >> 24) == b0) atomicAdd(&sh[(kv.x >> 16) & 255u], 1u);
        if ((kv.y >> 24) == b0) atomicAdd(&sh[(kv.y >> 16) & 255u], 1u);
        if ((kv.z >> 24) == b0) atomicAdd(&sh[(kv.z >> 16) & 255u], 1u);
        if ((kv.w >> 24) == b0) atomicAdd(&sh[(kv.w >> 16) & 255u], 1u);
    }
    __syncthreads();
    if (sh[tid]) atomicAdd(&g_m256[tid], sh[tid]);
    __threadfence();
    __syncthreads();
    if (tid == 0) {
        unsigned old = atomicAdd(&g_done[1], 1u);
        if (old == gridDim.x - 1) is_last = 1;
    }
    __syncthreads();
    if (is_last) {
        __shared__ unsigned sbin, srem;
        pick256(g_m256, (unsigned)g_counters[C_REM], &sbin, &srem, sh);
        if (tid == 0) {
            g_P16 = (g_B0 << 8) | sbin;
            g_counters[C_REM] = (int)srem;
        }
    }
}

// ---------------------------------------------------------------------------
// flag: classification + compaction; tail block runs eq_resolve inline.
// ---------------------------------------------------------------------------
__global__ void flag_kernel() {
    __shared__ int s_wsel[8], s_weq[8];
    __shared__ int s_osel[8], s_oeq[8];
    __shared__ int s_bsel, s_beq;
    __shared__ unsigned is_last;
    __shared__ unsigned hist[256];
    __shared__ unsigned suf[256];
    __shared__ unsigned sb, sneed;
    __shared__ int tie_idx[64];
    __shared__ unsigned tie_cnt;

    int tid = threadIdx.x;
    int wid = tid >> 5;
    int lane = tid & 31;
    if (tid == 0) is_last = 0;
    int i = blockIdx.x * blockDim.x + tid;
    bool valid = (i < N_NODES);
    unsigned k = valid ? g_keys[i] : 0u;
    unsigned p = k >> 16;
    unsigned P = g_P16;
    bool sel = valid && (p > P);
    bool eq = valid && (p == P);
    if (valid) g_flag[i] = sel ? 1 : 0;

    unsigned mSel = __ballot_sync(0xFFFFFFFFu, sel);
    unsigned mEq = __ballot_sync(0xFFFFFFFFu, eq);
    if (lane == 0) { s_wsel[wid] = __popc(mSel); s_weq[wid] = __popc(mEq); }
    __syncthreads();
    if (tid == 0) {
        int accS = 0, accE = 0;
#pragma unroll
        for (int wdx = 0; wdx < 8; wdx++) {
            s_osel[wdx] = accS; accS += s_wsel[wdx];
            s_oeq[wdx] = accE; accE += s_weq[wdx];
        }
        s_bsel = accS ? atomicAdd(&g_counters[C_SEL], accS) : 0;
        s_beq = accE ? atomicAdd(&g_counters[C_EQ], accE) : 0;
    }
    __syncthreads();
    unsigned lt = (1u << lane) - 1u;
    if (sel) {
        int pos = s_bsel + s_osel[wid] + __popc(mSel & lt);
        if (pos < S_SAMPLE + M_TILE) g_sel[pos] = i;
    }
    if (eq) {
        int pos = s_beq + s_oeq[wid] + __popc(mEq & lt);
        if (pos < EQCAP) g_eqPair[pos] = make_uint2(k, (unsigned)i);
    }

    __threadfence();
    __syncthreads();
    if (tid == 0) {
        unsigned old = atomicAdd(&g_done[2], 1u);
        if (old == gridDim.x - 1) is_last = 1;
    }
    __syncthreads();
    if (!is_last) return;

    int t = tid;
    int n = g_counters[C_EQ];
    if (n > EQCAP) n = EQCAP;
    unsigned d = (unsigned)g_counters[C_REM];

    hist[t] = 0;
    if (t == 0) tie_cnt = 0;
    __syncthreads();
    for (int j = t; j < n; j += 256)
        atomicAdd(&hist[(g_eqPair[j].x >> 8) & 255u], 1u);
    __syncthreads();
    pick256(hist, d, &sb, &sneed, suf);
    __syncthreads();
    unsigned b2 = sb, need3 = sneed;

    hist[t] = 0;
    __syncthreads();
    for (int j = t; j < n; j += 256) {
        unsigned kk = g_eqPair[j].x;
        if (((kk >> 8) & 255u) == b2) atomicAdd(&hist[kk & 255u], 1u);
    }
    __syncthreads();
    pick256(hist, need3, &sb, &sneed, suf);
    __syncthreads();
    unsigned T32 = (g_P16 << 16) | (b2 << 8) | sb;
    unsigned ties_needed = sneed;

    for (int j = t; j < n; j += 256) {
        uint2 pr = g_eqPair[j];
        if (pr.x > T32) {
            g_flag[pr.y] = 1;
            int q = atomicAdd(&g_counters[C_SEL], 1);
            if (q < S_SAMPLE + M_TILE) g_sel[q] = (int)pr.y;
        } else if (pr.x == T32) {
            unsigned e = atomicAdd(&tie_cnt, 1u);
            if (e < 64) tie_idx[e] = (int)pr.y;
        }
    }
    __syncthreads();
    int m = (tie_cnt < 64u) ? (int)tie_cnt : 64;
    if (t < m) {
        int idx = tie_idx[t];
        int rank = 0;
        for (int j = 0; j < m; j++) rank += (tie_idx[j] < idx) ? 1 : 0;
        if (rank < (int)ties_needed) {
            g_flag[idx] = 1;
            int q = atomicAdd(&g_counters[C_SEL], 1);
            if (q < S_SAMPLE + M_TILE) g_sel[q] = idx;
        }
    }
}

// ---------------------------------------------------------------------------
// HMMA GEMM, N-split for occupancy: block = 64 rows x 128 cols.
// Pairs (2g, 2g+1) share A rows (L2 reuse). Warp tile 32x32 -> 32 accum regs.
// B via cp.async (no prefetch regs, no STS). Inline loser-zeroing kept.
// ---------------------------------------------------------------------------
#define A_STRIDE 40
#define B_STRIDE 136   // halves; 272B rows
#define AS_HALF (M_TILE * A_STRIDE)
#define BS_HALF (32 * B_STRIDE)

__device__ __forceinline__ uint32_t smem_u32(const void* p) {
    uint32_t a;
    asm("{ .reg .u64 t; cvta.to.shared.u64 t, %1; cvt.u32.u64 %0, t; }"
        : "=r"(a) : "l"(p));
    return a;
}
#define CP_ASYNC16(dst, src) \
    asm volatile("cp.async.cg.shared.global [%0], [%1], 16;" \
                 :: "r"(dst), "l"(src) : "memory")
#define CP_COMMIT() asm volatile("cp.async.commit_group;" ::: "memory")
#define CP_WAIT0()  asm volatile("cp.async.wait_group 0;" ::: "memory")

__global__ void __launch_bounds__(256, 3) gemm_kernel(
    const float* __restrict__ x, const float* __restrict__ bias,
    float* __restrict__ out) {
    __shared__ __align__(16) __half As[2][AS_HALF];   // 10.2 KB
    __shared__ __align__(16) __half Bs[2][BS_HALF];   // 17.4 KB
    __shared__ int rows_s[M_TILE];
    __shared__ unsigned char zflag[ZROWS];

    int bid = blockIdx.x;
    int tid = threadIdx.x;
    int wid = tid >> 5;
    int lane = tid & 31;
    int gemm_id = bid >> 1;
    int n_off = (bid & 1) * 128;        // column half
    int r0 = gemm_id * M_TILE;
    int z0 = bid * ZROWS;

    if (tid < M_TILE) {
        int rr = r0 + tid;
        rows_s[tid] = g_sel[(rr < S_SAMPLE) ? rr : r0];
    }
    if (tid < ZROWS) {
        int zr = z0 + tid;
        zflag[tid] = (zr < N_NODES) ? g_flag[zr] : 1;
    }
    __syncthreads();

    int m_half = wid & 1;               // 0/1 -> rows 0-31 / 32-63
    int n_q = wid >> 1;                 // 0..3 -> 32-col group within the half

    float acc[2][4][4];
#pragma unroll
    for (int mt = 0; mt < 2; mt++)
#pragma unroll
        for (int nt = 0; nt < 4; nt++)
#pragma unroll
            for (int q = 0; q < 4; q++) acc[mt][nt][q] = 0.f;

    int a_row = tid >> 2;
    int a_part = (tid & 3) * 8;
    // B cp.async mapping: 512 x 16B per chunk; thread does units tid, tid+256
    int bu0 = tid;
    int bu1 = tid + 256;

    const uint32_t As_base = smem_u32(As);
    const uint32_t Bs_base = smem_u32(Bs);
    const float4* a_src = (const float4*)(x + (size_t)rows_s[a_row] * IN_C + a_part);
    const char* whBase = (const char*)g_wh + (size_t)(n_off / 2) * 4;

    // prefetch A chunk 0 (registers) + B chunk 0 (cp.async)
    float4 pa0 = a_src[0];
    float4 pa1 = a_src[1];
    {
        uint32_t d0 = Bs_base + ((bu0 >> 4) * B_STRIDE + (bu0 & 15) * 8) * 2;
        uint32_t d1 = Bs_base + ((bu1 >> 4) * B_STRIDE + (bu1 & 15) * 8) * 2;
        const char* s0 = whBase + ((size_t)(bu0 >> 4) * 512 + (bu0 & 15) * 16);
        const char* s1 = whBase + ((size_t)(bu1 >> 4) * 512 + (bu1 & 15) * 16);
        CP_ASYNC16(d0, s0);
        CP_ASYNC16(d1, s1);
        CP_COMMIT();
    }

    const float4 z4 = make_float4(0.f, 0.f, 0.f, 0.f);

    for (int kc = 0; kc < 8; kc++) {
        int buf = kc & 1;
        // store A chunk kc (from regs)
        {
            __half2 h0 = __floats2half2_rn(pa0.x, pa0.y);
            __half2 h1 = __floats2half2_rn(pa0.z, pa0.w);
            __half2 h2 = __floats2half2_rn(pa1.x, pa1.y);
            __half2 h3 = __floats2half2_rn(pa1.z, pa1.w);
            unsigned* dst = (unsigned*)&As[buf][a_row * A_STRIDE + a_part];
            dst[0] = *(unsigned*)&h0;
            dst[1] = *(unsigned*)&h1;
            dst[2] = *(unsigned*)&h2;
            dst[3] = *(unsigned*)&h3;
        }
        CP_WAIT0();        // B chunk kc complete
        __syncthreads();

        // prefetch chunk kc+1: A regs + B cp.async into other buffer
        if (kc < 7) {
            int k0n = (kc + 1) * 32;
            const float4* an = (const float4*)((const float*)a_src + k0n);
            pa0 = an[0];
            pa1 = an[1];
            int nb = (kc + 1) & 1;
            uint32_t bB = Bs_base + nb * (BS_HALF * 2);
            uint32_t d0 = bB + ((bu0 >> 4) * B_STRIDE + (bu0 & 15) * 8) * 2;
            uint32_t d1 = bB + ((bu1 >> 4) * B_STRIDE + (bu1 & 15) * 8) * 2;
            const char* sBase = whBase + (size_t)k0n * 512;
            const char* s0 = sBase + ((size_t)(bu0 >> 4) * 512 + (bu0 & 15) * 16);
            const char* s1 = sBase + ((size_t)(bu1 >> 4) * 512 + (bu1 & 15) * 16);
            CP_ASYNC16(d0, s0);
            CP_ASYNC16(d1, s1);
            CP_COMMIT();
        }

        // inline zeroing: 20 rows this chunk (fire-and-forget)
        for (int zi = wid; zi < ZCHUNK; zi += 8) {
            int zl = kc * ZCHUNK + zi;
            int row = z0 + zl;
            if (row < N_NODES && !zflag[zl]) {
                float4* pr = (float4*)(out + (size_t)row * OUT_C);
                pr[lane] = z4;
                pr[lane + 32] = z4;
            }
        }

        uint32_t aBufBase = As_base + buf * (AS_HALF * 2);
        uint32_t bBufBase = Bs_base + buf * (BS_HALF * 2);
#pragma unroll
        for (int ks = 0; ks < 2; ks++) {
            uint32_t af[2][4];
#pragma unroll
            for (int mt = 0; mt < 2; mt++) {
                int row = m_half * 32 + mt * 16 + (lane & 15);
                int col = ks * 16 + (lane >> 4) * 8;
                uint32_t addr = aBufBase + (row * A_STRIDE + col) * 2;
                asm volatile(
                    "ldmatrix.sync.aligned.m8n8.x4.shared.b16 {%0,%1,%2,%3}, [%4];"
                    : "=r"(af[mt][0]), "=r"(af[mt][1]),
                      "=r"(af[mt][2]), "=r"(af[mt][3]) : "r"(addr));
            }
            uint32_t bf[4][2];
#pragma unroll
            for (int nt = 0; nt < 4; nt++) {
                int krow = ks * 16 + (lane & 15);
                int ncol = n_q * 32 + nt * 8;
                uint32_t addr = bBufBase + (krow * B_STRIDE + ncol) * 2;
                asm volatile(
                    "ldmatrix.sync.aligned.m8n8.x2.trans.shared.b16 {%0,%1}, [%2];"
                    : "=r"(bf[nt][0]), "=r"(bf[nt][1]) : "r"(addr));
            }
#pragma unroll
            for (int mt = 0; mt < 2; mt++)
#pragma unroll
                for (int nt = 0; nt < 4; nt++) {
                    asm volatile(
                        "mma.sync.aligned.m16n8k16.row.col.f32.f16.f16.f32 "
                        "{%0,%1,%2,%3}, {%4,%5,%6,%7}, {%8,%9}, {%0,%1,%2,%3};"
                        : "+f"(acc[mt][nt][0]), "+f"(acc[mt][nt][1]),
                          "+f"(acc[mt][nt][2]), "+f"(acc[mt][nt][3])
                        : "r"(af[mt][0]), "r"(af[mt][1]),
                          "r"(af[mt][2]), "r"(af[mt][3]),
                          "r"(bf[nt][0]), "r"(bf[nt][1]));
                }
        }
        if (kc < 7) __syncthreads();
    }

    const float scale = 5.0f;
    int qr = lane >> 2;
    int qc = (lane & 3) * 2;
#pragma unroll
    for (int mt = 0; mt < 2; mt++) {
        int lrow_lo = m_half * 32 + mt * 16 + qr;
        int g_lo = rows_s[lrow_lo];
        int g_hi = rows_s[lrow_lo + 8];
        float* row_lo = out + (size_t)g_lo * OUT_C;
        float* row_hi = out + (size_t)g_hi * OUT_C;
#pragma unroll
        for (int nt = 0; nt < 4; nt++) {
            int col = n_off + n_q * 32 + nt * 8 + qc;
            float b0 = bias[col], b1 = bias[col + 1];
            *(float2*)(row_lo + col) = make_float2(
                (acc[mt][nt][0] + b0) * scale, (acc[mt][nt][1] + b1) * scale);
            *(float2*)(row_hi + col) = make_float2(
                (acc[mt][nt][2] + b0) * scale, (acc[mt][nt][3] + b1) * scale);
        }
    }

    // cleanup for next replay
    if (bid == 0) {
        g_c256[tid] = 0;
        g_m256[tid] = 0;
        if (tid < 4) g_counters[tid] = 0;
        if (tid < 3) g_done[tid] = 0;
    }
}

// ---------------------------------------------------------------------------
// Launch (4 kernels)
// ---------------------------------------------------------------------------
extern "C" void kernel_launch(void* const* d_in, const int* in_sizes, int n_in,
                              void* d_out, int out_size) {
    const float* x = nullptr;
    const float* w = nullptr;
    const float* bias = nullptr;
    const float* imp = nullptr;
    for (int i = 0; i < n_in; i++) {
        switch (in_sizes[i]) {
            case 128000000: x = (const float*)d_in[i]; break;
            case 65536:     w = (const float*)d_in[i]; break;
            case 256:       bias = (const float*)d_in[i]; break;
            case 500000:    imp = (const float*)d_in[i]; break;
            default: break;  // edge_index unused
        }
    }
    float* out = (float*)d_out;
    (void)out_size;

    score_kernel<<<(N_NODES + 255) / 256, 256>>>(imp, w);
    hist2_kernel<<<(N_NODES / 4 + 255) / 256, 256>>>();
    flag_kernel<<<(N_NODES + 255) / 256, 256>>>();
    gemm_kernel<<<NGEMM, 256>>>(x, bias, out);
}

// round 17
// speedup vs baseline: 1.5165x; 1.0054x over previous
#include <cuda_runtime.h>
#include <cuda_fp16.h>
#include <cstdint>

// ---------------------------------------------------------------------------
// Problem constants
// ---------------------------------------------------------------------------
#define N_NODES 500000
#define S_SAMPLE 100000
#define EQCAP 32768
#define OUT_C 256
#define IN_C 256
#define M_TILE 64
#define NBLK ((S_SAMPLE + M_TILE - 1) / M_TILE)   // 1563
#define NGEMM (2 * NBLK)                          // 3126 (N split in halves)
#define ZROWS 160
#define ZCHUNK 20

// libdevice accurate log (immune to fast-math logf substitution)
extern "C" __device__ float __nv_logf(float);

// ---------------------------------------------------------------------------
// Device scratch (zero-initialized at load; gemm block 0 re-zeroes the
// counters at the END of each call -> clean state for the next graph replay)
// ---------------------------------------------------------------------------
__device__ unsigned g_keys[N_NODES];
__device__ unsigned char g_flag[N_NODES];   // 1 = row written by gemm
__device__ int g_sel[S_SAMPLE + M_TILE];
__device__ uint2 g_eqPair[EQCAP];           // (key, idx)
__device__ unsigned g_c256[256];
__device__ unsigned g_m256[256];
__device__ unsigned g_B0;
__device__ unsigned g_P16;
__device__ int g_counters[4];
__device__ unsigned g_done[3];
__device__ unsigned g_wh[32768];            // w as f16 pairs, [k][n]
#define C_SEL 0
#define C_EQ 1
#define C_REM 2

// ---------------------------------------------------------------------------
// Threefry-2x32, partitionable: x0=0, x1=i, key=(0,42); draw = out0 ^ out1
// ---------------------------------------------------------------------------
__device__ __forceinline__ unsigned rotl32(unsigned x, int r) {
    return (x << r) | (x >> (32 - r));
}
__device__ __forceinline__ unsigned threefry_bits(unsigned i) {
    const unsigned ks0 = 0u, ks1 = 42u;
    const unsigned ks2 = 0x1BD11BDAu ^ ks0 ^ ks1;
    unsigned x0 = 0u + ks0;
    unsigned x1 = i + ks1;
#define TF_R4(a, b, c, d)                                   \
    x0 += x1; x1 = rotl32(x1, a); x1 ^= x0;                 \
    x0 += x1; x1 = rotl32(x1, b); x1 ^= x0;                 \
    x0 += x1; x1 = rotl32(x1, c); x1 ^= x0;                 \
    x0 += x1; x1 = rotl32(x1, d); x1 ^= x0;
    TF_R4(13, 15, 26, 6)  x0 += ks1; x1 += ks2 + 1u;
    TF_R4(17, 29, 16, 24) x0 += ks2; x1 += ks0 + 2u;
    TF_R4(13, 15, 26, 6)  x0 += ks0; x1 += ks1 + 3u;
    TF_R4(17, 29, 16, 24) x0 += ks1; x1 += ks2 + 4u;
    TF_R4(13, 15, 26, 6)  x0 += ks2; x1 += ks0 + 5u;
#undef TF_R4
    return x0 ^ x1;
}
__device__ __forceinline__ unsigned f2key(float f) {
    unsigned b = __float_as_uint(f);
    return (b & 0x80000000u) ? ~b : (b | 0x80000000u);
}

// ---------------------------------------------------------------------------
// suffix-scan pick over a 256-bin hist (in-block)
// ---------------------------------------------------------------------------
__device__ void pick256(const unsigned* hist, unsigned need,
                        unsigned* out_bin, unsigned* out_rem, unsigned* suf) {
    int t = threadIdx.x;
    suf[t] = hist[t];
    __syncthreads();
#pragma unroll
    for (int off = 1; off < 256; off <<= 1) {
        unsigned v = (t + off < 256) ? suf[t + off] : 0u;
        __syncthreads();
        suf[t] += v;
        __syncthreads();
    }
    unsigned above = (t < 255) ? suf[t + 1] : 0u;
    if (suf[t] >= need && above < need) {
        *out_bin = (unsigned)t;
        *out_rem = need - above;
        __threadfence();
    }
    __syncthreads();
}

// ---------------------------------------------------------------------------
// score: keys + coarse hist + fused pick8 in tail block + w conversion
// ---------------------------------------------------------------------------
__global__ void score_kernel(const float* __restrict__ imp,
                             const float* __restrict__ w) {
    __shared__ unsigned sh[256];
    __shared__ unsigned is_last;
    int tid = threadIdx.x;
    sh[tid] = 0;
    if (tid == 0) is_last = 0;
    __syncthreads();
    if (blockIdx.x < 128) {
        int t = blockIdx.x * 256 + tid;
        float2 v = ((const float2*)w)[t];
        __half2 h = __floats2half2_rn(v.x, v.y);
        g_wh[t] = *(unsigned*)&h;
    }
    int i = blockIdx.x * blockDim.x + tid;
    if (i < N_NODES) {
        unsigned bits = threefry_bits((unsigned)i);
        float f = __uint_as_float((bits >> 9) | 0x3F800000u) - 1.0f;
        float u = f + 1.17549435e-38f;
        float g = -__nv_logf(-__nv_logf(u));
        unsigned k = f2key(__nv_logf(imp[i]) + g);
        g_keys[i] = k;
        atomicAdd(&sh[k >> 24], 1u);
    }
    __syncthreads();
    if (sh[tid]) atomicAdd(&g_c256[tid], sh[tid]);
    __threadfence();
    __syncthreads();
    if (tid == 0) {
        unsigned old = atomicAdd(&g_done[0], 1u);
        if (old == gridDim.x - 1) is_last = 1;
    }
    __syncthreads();
    if (is_last)
        pick256(g_c256, S_SAMPLE, &g_B0, (unsigned*)&g_counters[C_REM], sh);
}

// ---------------------------------------------------------------------------
// hist2: bits[23:16] hist among keys with top byte == B0 (+ fused pick16)
// ---------------------------------------------------------------------------
__global__ void hist2_kernel() {
    __shared__ unsigned sh[256];
    __shared__ unsigned is_last;
    int tid = threadIdx.x;
    sh[tid] = 0;
    if (tid == 0) is_last = 0;
    __syncthreads();
    unsigned b0 = g_B0;
    int j = blockIdx.x * blockDim.x + tid;
    if (j < N_NODES / 4) {
        uint4 kv = ((const uint4*)g_keys)[j];
        if ((kv.x >> 24) == b0) atomicAdd(&sh[(kv.x >> 16) & 255u], 1u);
        if ((kv.y >> 24) == b0) atomicAdd(&sh[(kv.y >> 16) & 255u], 1u);
        if ((kv.z >> 24) == b0) atomicAdd(&sh[(kv.z >> 16) & 255u], 1u);
        if ((kv.w >> 24) == b0) atomicAdd(&sh[(kv.w >> 16) & 255u], 1u);
    }
    __syncthreads();
    if (sh[tid]) atomicAdd(&g_m256[tid], sh[tid]);
    __threadfence();
    __syncthreads();
    if (tid == 0) {
        unsigned old = atomicAdd(&g_done[1], 1u);
        if (old == gridDim.x - 1) is_last = 1;
    }
    __syncthreads();
    if (is_last) {
        __shared__ unsigned sbin, srem;
        pick256(g_m256, (unsigned)g_counters[C_REM], &sbin, &srem, sh);
        if (tid == 0) {
            g_P16 = (g_B0 << 8) | sbin;
            g_counters[C_REM] = (int)srem;
        }
    }
}

// ---------------------------------------------------------------------------
// flag: classification + compaction; tail block runs eq_resolve inline.
// ---------------------------------------------------------------------------
__global__ void flag_kernel() {
    __shared__ int s_wsel[8], s_weq[8];
    __shared__ int s_osel[8], s_oeq[8];
    __shared__ int s_bsel, s_beq;
    __shared__ unsigned is_last;
    __shared__ unsigned hist[256];
    __shared__ unsigned suf[256];
    __shared__ unsigned sb, sneed;
    __shared__ int tie_idx[64];
    __shared__ unsigned tie_cnt;

    int tid = threadIdx.x;
    int wid = tid >> 5;
    int lane = tid & 31;
    if (tid == 0) is_last = 0;
    int i = blockIdx.x * blockDim.x + tid;
    bool valid = (i < N_NODES);
    unsigned k = valid ? g_keys[i] : 0u;
    unsigned p = k >> 16;
    unsigned P = g_P16;
    bool sel = valid && (p > P);
    bool eq = valid && (p == P);
    if (valid) g_flag[i] = sel ? 1 : 0;

    unsigned mSel = __ballot_sync(0xFFFFFFFFu, sel);
    unsigned mEq = __ballot_sync(0xFFFFFFFFu, eq);
    if (lane == 0) { s_wsel[wid] = __popc(mSel); s_weq[wid] = __popc(mEq); }
    __syncthreads();
    if (tid == 0) {
        int accS = 0, accE = 0;
#pragma unroll
        for (int wdx = 0; wdx < 8; wdx++) {
            s_osel[wdx] = accS; accS += s_wsel[wdx];
            s_oeq[wdx] = accE; accE += s_weq[wdx];
        }
        s_bsel = accS ? atomicAdd(&g_counters[C_SEL], accS) : 0;
        s_beq = accE ? atomicAdd(&g_counters[C_EQ], accE) : 0;
    }
    __syncthreads();
    unsigned lt = (1u << lane) - 1u;
    if (sel) {
        int pos = s_bsel + s_osel[wid] + __popc(mSel & lt);
        if (pos < S_SAMPLE + M_TILE) g_sel[pos] = i;
    }
    if (eq) {
        int pos = s_beq + s_oeq[wid] + __popc(mEq & lt);
        if (pos < EQCAP) g_eqPair[pos] = make_uint2(k, (unsigned)i);
    }

    __threadfence();
    __syncthreads();
    if (tid == 0) {
        unsigned old = atomicAdd(&g_done[2], 1u);
        if (old == gridDim.x - 1) is_last = 1;
    }
    __syncthreads();
    if (!is_last) return;

    int t = tid;
    int n = g_counters[C_EQ];
    if (n > EQCAP) n = EQCAP;
    unsigned d = (unsigned)g_counters[C_REM];

    hist[t] = 0;
    if (t == 0) tie_cnt = 0;
    __syncthreads();
    for (int j = t; j < n; j += 256)
        atomicAdd(&hist[(g_eqPair[j].x >> 8) & 255u], 1u);
    __syncthreads();
    pick256(hist, d, &sb, &sneed, suf);
    __syncthreads();
    unsigned b2 = sb, need3 = sneed;

    hist[t] = 0;
    __syncthreads();
    for (int j = t; j < n; j += 256) {
        unsigned kk = g_eqPair[j].x;
        if (((kk >> 8) & 255u) == b2) atomicAdd(&hist[kk & 255u], 1u);
    }
    __syncthreads();
    pick256(hist, need3, &sb, &sneed, suf);
    __syncthreads();
    unsigned T32 = (g_P16 << 16) | (b2 << 8) | sb;
    unsigned ties_needed = sneed;

    for (int j = t; j < n; j += 256) {
        uint2 pr = g_eqPair[j];
        if (pr.x > T32) {
            g_flag[pr.y] = 1;
            int q = atomicAdd(&g_counters[C_SEL], 1);
            if (q < S_SAMPLE + M_TILE) g_sel[q] = (int)pr.y;
        } else if (pr.x == T32) {
            unsigned e = atomicAdd(&tie_cnt, 1u);
            if (e < 64) tie_idx[e] = (int)pr.y;
        }
    }
    __syncthreads();
    int m = (tie_cnt < 64u) ? (int)tie_cnt : 64;
    if (t < m) {
        int idx = tie_idx[t];
        int rank = 0;
        for (int j = 0; j < m; j++) rank += (tie_idx[j] < idx) ? 1 : 0;
        if (rank < (int)ties_needed) {
            g_flag[idx] = 1;
            int q = atomicAdd(&g_counters[C_SEL], 1);
            if (q < S_SAMPLE + M_TILE) g_sel[q] = idx;
        }
    }
}

// ---------------------------------------------------------------------------
// HMMA GEMM, N-split (64 rows x 128 cols/block); ALL global loads via
// cp.async (A into f32 staging + smem convert; B direct) -> no long-lived
// prefetch registers -> 4 blocks/SM. Inline loser-zeroing kept.
// ---------------------------------------------------------------------------
#define A_STRIDE 40
#define B_STRIDE 136   // halves; 272B rows
#define AST_STRIDE 36  // f32 staging stride (bank-stagger)
#define AS_HALF (M_TILE * A_STRIDE)
#define BS_HALF (32 * B_STRIDE)

__device__ __forceinline__ uint32_t smem_u32(const void* p) {
    uint32_t a;
    asm("{ .reg .u64 t; cvta.to.shared.u64 t, %1; cvt.u32.u64 %0, t; }"
        : "=r"(a) : "l"(p));
    return a;
}
#define CP_ASYNC16(dst, src) \
    asm volatile("cp.async.cg.shared.global [%0], [%1], 16;" \
                 :: "r"(dst), "l"(src) : "memory")
#define CP_COMMIT() asm volatile("cp.async.commit_group;" ::: "memory")
#define CP_WAIT0()  asm volatile("cp.async.wait_group 0;" ::: "memory")

__global__ void __launch_bounds__(256, 4) gemm_kernel(
    const float* __restrict__ x, const float* __restrict__ bias,
    float* __restrict__ out) {
    __shared__ __align__(16) __half As[2][AS_HALF];        // 10.2 KB
    __shared__ __align__(16) __half Bs[2][BS_HALF];        // 17.4 KB
    __shared__ __align__(16) float Ast[2][M_TILE * AST_STRIDE]; // 18.4 KB
    __shared__ int rows_s[M_TILE];
    __shared__ unsigned char zflag[ZROWS];

    int bid = blockIdx.x;
    int tid = threadIdx.x;
    int wid = tid >> 5;
    int lane = tid & 31;
    int gemm_id = bid >> 1;
    int n_off = (bid & 1) * 128;
    int r0 = gemm_id * M_TILE;
    int z0 = bid * ZROWS;

    if (tid < M_TILE) {
        int rr = r0 + tid;
        rows_s[tid] = g_sel[(rr < S_SAMPLE) ? rr : r0];
    }
    if (tid < ZROWS) {
        int zr = z0 + tid;
        zflag[tid] = (zr < N_NODES) ? g_flag[zr] : 1;
    }
    __syncthreads();

    int m_half = wid & 1;
    int n_q = wid >> 1;

    float acc[2][4][4];
#pragma unroll
    for (int mt = 0; mt < 2; mt++)
#pragma unroll
        for (int nt = 0; nt < 4; nt++)
#pragma unroll
            for (int q = 0; q < 4; q++) acc[mt][nt][q] = 0.f;

    int a_row = tid >> 2;
    int a_part = (tid & 3) * 8;
    int bu0 = tid;
    int bu1 = tid + 256;

    const uint32_t As_base = smem_u32(As);
    const uint32_t Bs_base = smem_u32(Bs);
    const uint32_t Ast_base = smem_u32(Ast);
    const char* aSrc = (const char*)(x + (size_t)rows_s[a_row] * IN_C + a_part);
    const char* whBase = (const char*)g_wh + (size_t)(n_off / 2) * 4;

    uint32_t astDst = Ast_base + (a_row * AST_STRIDE + a_part) * 4;
    uint32_t bD0off = ((bu0 >> 4) * B_STRIDE + (bu0 & 15) * 8) * 2;
    uint32_t bD1off = ((bu1 >> 4) * B_STRIDE + (bu1 & 15) * 8) * 2;
    size_t bS0off = (size_t)(bu0 >> 4) * 512 + (bu0 & 15) * 16;
    size_t bS1off = (size_t)(bu1 >> 4) * 512 + (bu1 & 15) * 16;

    // prefetch chunk 0 (A staging + B) via cp.async
    CP_ASYNC16(astDst, aSrc);
    CP_ASYNC16(astDst + 16, aSrc + 16);
    CP_ASYNC16(Bs_base + bD0off, whBase + bS0off);
    CP_ASYNC16(Bs_base + bD1off, whBase + bS1off);
    CP_COMMIT();

    const float4 z4 = make_float4(0.f, 0.f, 0.f, 0.f);

    for (int kc = 0; kc < 8; kc++) {
        int buf = kc & 1;
        CP_WAIT0();
        __syncthreads();   // staging[buf] + Bs[buf] complete & visible

        // convert A staging (f32) -> As (f16)
        {
            const float4* st = (const float4*)&Ast[buf][a_row * AST_STRIDE + a_part];
            float4 v0 = st[0];
            float4 v1 = st[1];
            __half2 h0 = __floats2half2_rn(v0.x, v0.y);
            __half2 h1 = __floats2half2_rn(v0.z, v0.w);
            __half2 h2 = __floats2half2_rn(v1.x, v1.y);
            __half2 h3 = __floats2half2_rn(v1.z, v1.w);
            unsigned* dst = (unsigned*)&As[buf][a_row * A_STRIDE + a_part];
            dst[0] = *(unsigned*)&h0;
            dst[1] = *(unsigned*)&h1;
            dst[2] = *(unsigned*)&h2;
            dst[3] = *(unsigned*)&h3;
        }

        // prefetch chunk kc+1 into the other buffers (hidden under MMA)
        if (kc < 7) {
            int nb = buf ^ 1;
            const char* aN = aSrc + (size_t)(kc + 1) * 128;
            uint32_t astN = Ast_base + nb * (M_TILE * AST_STRIDE * 4) +
                            (a_row * AST_STRIDE + a_part) * 4;
            const char* bN = whBase + (size_t)(kc + 1) * 32 * 512;
            uint32_t bB = Bs_base + nb * (BS_HALF * 2);
            CP_ASYNC16(astN, aN);
            CP_ASYNC16(astN + 16, aN + 16);
            CP_ASYNC16(bB + bD0off, bN + bS0off);
            CP_ASYNC16(bB + bD1off, bN + bS1off);
            CP_COMMIT();
        }
        __syncthreads();   // As[buf] stores visible

        // inline zeroing (fire-and-forget)
        for (int zi = wid; zi < ZCHUNK; zi += 8) {
            int zl = kc * ZCHUNK + zi;
            int row = z0 + zl;
            if (row < N_NODES && !zflag[zl]) {
                float4* pr = (float4*)(out + (size_t)row * OUT_C);
                pr[lane] = z4;
                pr[lane + 32] = z4;
            }
        }

        uint32_t aBufBase = As_base + buf * (AS_HALF * 2);
        uint32_t bBufBase = Bs_base + buf * (BS_HALF * 2);
#pragma unroll
        for (int ks = 0; ks < 2; ks++) {
            uint32_t af[2][4];
#pragma unroll
            for (int mt = 0; mt < 2; mt++) {
                int row = m_half * 32 + mt * 16 + (lane & 15);
                int col = ks * 16 + (lane >> 4) * 8;
                uint32_t addr = aBufBase + (row * A_STRIDE + col) * 2;
                asm volatile(
                    "ldmatrix.sync.aligned.m8n8.x4.shared.b16 {%0,%1,%2,%3}, [%4];"
                    : "=r"(af[mt][0]), "=r"(af[mt][1]),
                      "=r"(af[mt][2]), "=r"(af[mt][3]) : "r"(addr));
            }
            uint32_t bf[4][2];
#pragma unroll
            for (int nt = 0; nt < 4; nt++) {
                int krow = ks * 16 + (lane & 15);
                int ncol = n_q * 32 + nt * 8;
                uint32_t addr = bBufBase + (krow * B_STRIDE + ncol) * 2;
                asm volatile(
                    "ldmatrix.sync.aligned.m8n8.x2.trans.shared.b16 {%0,%1}, [%2];"
                    : "=r"(bf[nt][0]), "=r"(bf[nt][1]) : "r"(addr));
            }
#pragma unroll
            for (int mt = 0; mt < 2; mt++)
#pragma unroll
                for (int nt = 0; nt < 4; nt++) {
                    asm volatile(
                        "mma.sync.aligned.m16n8k16.row.col.f32.f16.f16.f32 "
                        "{%0,%1,%2,%3}, {%4,%5,%6,%7}, {%8,%9}, {%0,%1,%2,%3};"
                        : "+f"(acc[mt][nt][0]), "+f"(acc[mt][nt][1]),
                          "+f"(acc[mt][nt][2]), "+f"(acc[mt][nt][3])
                        : "r"(af[mt][0]), "r"(af[mt][1]),
                          "r"(af[mt][2]), "r"(af[mt][3]),
                          "r"(bf[nt][0]), "r"(bf[nt][1]));
                }
        }
    }

    const float scale = 5.0f;
    int qr = lane >> 2;
    int qc = (lane & 3) * 2;
#pragma unroll
    for (int mt = 0; mt < 2; mt++) {
        int lrow_lo = m_half * 32 + mt * 16 + qr;
        int g_lo = rows_s[lrow_lo];
        int g_hi = rows_s[lrow_lo + 8];
        float* row_lo = out + (size_t)g_lo * OUT_C;
        float* row_hi = out + (size_t)g_hi * OUT_C;
#pragma unroll
        for (int nt = 0; nt < 4; nt++) {
            int col = n_off + n_q * 32 + nt * 8 + qc;
            float b0 = bias[col], b1 = bias[col + 1];
            *(float2*)(row_lo + col) = make_float2(
                (acc[mt][nt][0] + b0) * scale, (acc[mt][nt][1] + b1) * scale);
            *(float2*)(row_hi + col) = make_float2(
                (acc[mt][nt][2] + b0) * scale, (acc[mt][nt][3] + b1) * scale);
        }
    }

    // cleanup for next replay
    if (bid == 0) {
        g_c256[tid] = 0;
        g_m256[tid] = 0;
        if (tid < 4) g_counters[tid] = 0;
        if (tid < 3) g_done[tid] = 0;
    }
}

// ---------------------------------------------------------------------------
// Launch (4 kernels)
// ---------------------------------------------------------------------------
extern "C" void kernel_launch(void* const* d_in, const int* in_sizes, int n_in,
                              void* d_out, int out_size) {
    const float* x = nullptr;
    const float* w = nullptr;
    const float* bias = nullptr;
    const float* imp = nullptr;
    for (int i = 0; i < n_in; i++) {
        switch (in_sizes[i]) {
            case 128000000: x = (const float*)d_in[i]; break;
            case 65536:     w = (const float*)d_in[i]; break;
            case 256:       bias = (const float*)d_in[i]; break;
            case 500000:    imp = (const float*)d_in[i]; break;
            default: break;  // edge_index unused
        }
    }
    float* out = (float*)d_out;
    (void)out_size;

    score_kernel<<<(N_NODES + 255) / 256, 256>>>(imp, w);
    hist2_kernel<<<(N_NODES / 4 + 255) / 256, 256>>>();
    flag_kernel<<<(N_NODES + 255) / 256, 256>>>();
    gemm_kernel<<<NGEMM, 256>>>(x, bias, out);
}